// round 9
// baseline (speedup 1.0000x reference)
#include <cuda_runtime.h>
#include <cuda_fp16.h>
#include <math.h>
#include <stdint.h>

#define B_ 2
#define S_ 2048
#define D_ 768
#define H_ 12
#define HD_ 64
#define FF_ 3072
#define L_ 12
#define M_ (B_*S_)   // 4096 rows
#define D3_ (3*D_)   // 2304

// ---------------- scratch (device globals; no allocation allowed) ----------
__device__ float g_x[M_*D_];
__device__ float g_t[M_*D_];

__device__ __align__(16) __half g_xh[M_*D_];     // fp16 x (GEMM A input)
__device__ __align__(16) __half g_ah[M_*D_];     // fp16 attention out
__device__ __align__(16) __half g_hh[M_*FF_];    // fp16 gelu out
__device__ __align__(16) __half g_qkv[M_*D3_];   // fused q|k|v rows
// transposed fp16 weights, ALL layers
__device__ __align__(16) __half g_wqkv[L_*D3_*D_];  // [L][2304][768]
__device__ __align__(16) __half g_wo[L_*D_*D_];
__device__ __align__(16) __half g_w1[L_*FF_*D_];    // N=3072,K=768
__device__ __align__(16) __half g_w2[L_*D_*FF_];    // N=768,K=3072
__device__ float g_bqkv[L_*D3_];

// ---------------- PTX helpers (base-target safe) ----------------
__device__ __forceinline__ uint32_t smem_u32(const void* p) {
    uint32_t a;
    asm("{ .reg .u64 t; cvta.to.shared.u64 t, %1; cvt.u32.u64 %0, t; }" : "=r"(a) : "l"(p));
    return a;
}
__device__ __forceinline__ void cp16(uint32_t s, const void* g) {
    asm volatile("cp.async.cg.shared.global [%0], [%1], 16;" :: "r"(s), "l"(g));
}
#define CP_COMMIT()  asm volatile("cp.async.commit_group;" ::: "memory")
#define CP_WAIT(n)   asm volatile("cp.async.wait_group %0;" :: "n"(n) : "memory")

__device__ __forceinline__ void ldm4(uint32_t* r, uint32_t addr) {
    asm volatile("ldmatrix.sync.aligned.m8n8.x4.shared.b16 {%0,%1,%2,%3}, [%4];"
        : "=r"(r[0]), "=r"(r[1]), "=r"(r[2]), "=r"(r[3]) : "r"(addr));
}
__device__ __forceinline__ void mma16816(float* c, const uint32_t* a, uint32_t b0, uint32_t b1) {
    asm volatile("mma.sync.aligned.m16n8k16.row.col.f32.f16.f16.f32 "
        "{%0,%1,%2,%3}, {%4,%5,%6,%7}, {%8,%9}, {%0,%1,%2,%3};"
        : "+f"(c[0]), "+f"(c[1]), "+f"(c[2]), "+f"(c[3])
        : "r"(a[0]), "r"(a[1]), "r"(a[2]), "r"(a[3]), "r"(b0), "r"(b1));
}

// ---------------- batched weight transpose -------------------------------
__global__ void ttrans_all(const float* __restrict__ W, __half* __restrict__ T,
                           int K, int N, size_t lsW, size_t lsT) {
    __shared__ float t[32][33];
    int li = blockIdx.z;
    const float* Wl = W + (size_t)li * lsW;
    __half* Tl = T + (size_t)li * lsT;
    int k0 = blockIdx.y * 32, n0 = blockIdx.x * 32;
    int tx = threadIdx.x & 31, ty = threadIdx.x >> 5;  // 32 x 8
#pragma unroll
    for (int i = 0; i < 4; i++)
        t[ty + i * 8][tx] = Wl[(size_t)(k0 + ty + i * 8) * N + n0 + tx];
    __syncthreads();
#pragma unroll
    for (int i = 0; i < 4; i++)
        Tl[(size_t)(n0 + ty + i * 8) * K + k0 + tx] = __float2half(t[tx][ty + i * 8]);
}

// concat biases: [L][D] x3 -> [L][3D]
__global__ void bcat_kernel(const float* __restrict__ bq, const float* __restrict__ bk,
                            const float* __restrict__ bv) {
    int i = blockIdx.x * blockDim.x + threadIdx.x;
    if (i >= L_ * D3_) return;
    int li = i / D3_, r = i % D3_;
    int sec = r / D_, d = r % D_;
    const float* src = sec == 0 ? bq : (sec == 1 ? bk : bv);
    g_bqkv[i] = src[li * D_ + d];
}

__device__ __forceinline__ float gelu_f(float c) {
    return 0.5f * c * (1.0f + erff(c * 0.70710678118654752f));
}

// ================= GEMM variant A: CTA 256x128 (big N) ====================
#define PITCH   80
#define TA      (256*PITCH)        // 20480
#define TB      (128*PITCH)        // 10240
#define STAGE   (TA+TB)            // 30720
#define GSMEM   (2*STAGE)          // 61440

__device__ __forceinline__ void load_chunk(uint32_t sbase,
                                           const __half* pA, const __half* pB,
                                           int K, int tid) {
#pragma unroll
    for (int e = 0; e < 4; e++) {
        int idx = tid + e * 256;
        int r = idx >> 2, ch = idx & 3;
        cp16(sbase + r * PITCH + ch * 16, pA + (size_t)r * K + ch * 8);
    }
#pragma unroll
    for (int e = 0; e < 2; e++) {
        int idx = tid + e * 256;
        int r = idx >> 2, ch = idx & 3;
        cp16(sbase + TA + r * PITCH + ch * 16, pB + (size_t)r * K + ch * 8);
    }
}

__global__ void __launch_bounds__(256, 1)
gemm_h(const __half* __restrict__ A, const __half* __restrict__ Bt,
       const float* __restrict__ bias, const float* __restrict__ res,
       void* __restrict__ Cv, int N, int K, int epi) {
    extern __shared__ __align__(16) char smem[];
    uint32_t sb = smem_u32(smem);
    int tid = threadIdx.x, wid = tid >> 5, lane = tid & 31;
    int wm = wid >> 1, wn = wid & 1;       // warp tile: 64 x 64
    int m0 = blockIdx.y * 256, n0 = blockIdx.x * 128;

    const __half* pA = A  + (size_t)m0 * K;
    const __half* pB = Bt + (size_t)n0 * K;

    float acc[4][8][4] = {};

    const int NC = K / 32;
    load_chunk(sb, pA, pB, K, tid);
    CP_COMMIT();

    int lrow = lane & 15;
    int lch  = (lane >> 4) * 16;

    for (int c = 0; c < NC; c++) {
        uint32_t st = sb + (c & 1) * STAGE;
        if (c + 1 < NC) {
            load_chunk(sb + ((c + 1) & 1) * STAGE, pA + (c+1)*32, pB + (c+1)*32, K, tid);
            CP_COMMIT();
            CP_WAIT(1);
        } else {
            CP_WAIT(0);
        }
        __syncthreads();

#pragma unroll
        for (int ks = 0; ks < 2; ks++) {
            uint32_t ah[4][4], bh[4][4];
#pragma unroll
            for (int mi = 0; mi < 4; mi++) {
                uint32_t off = (uint32_t)(wm*64 + mi*16 + lrow) * PITCH + ks*32 + lch;
                ldm4(ah[mi], st + off);
            }
#pragma unroll
            for (int np = 0; np < 4; np++) {
                uint32_t off = (uint32_t)(wn*64 + np*16 + lrow) * PITCH + ks*32 + lch;
                ldm4(bh[np], st + TA + off);
            }
#pragma unroll
            for (int mi = 0; mi < 4; mi++)
#pragma unroll
                for (int ni = 0; ni < 8; ni++) {
                    int np = ni >> 1, sel = ni & 1;
                    mma16816(acc[mi][ni], ah[mi], bh[np][sel], bh[np][sel + 2]);
                }
        }
        __syncthreads();
    }

    int qrow = lane >> 2, qcol = (lane & 3) * 2;
#pragma unroll
    for (int mi = 0; mi < 4; mi++) {
#pragma unroll
        for (int ni = 0; ni < 8; ni++) {
            int row = m0 + wm*64 + mi*16 + qrow;
            int col = n0 + wn*64 + ni*8 + qcol;
            float b0 = bias[col], b1 = bias[col + 1];
#pragma unroll
            for (int hh = 0; hh < 2; hh++) {
                int r = row + hh * 8;
                float v0 = acc[mi][ni][hh*2 + 0] + b0;
                float v1 = acc[mi][ni][hh*2 + 1] + b1;
                if (epi == 1) {
                    v0 = gelu_f(v0); v1 = gelu_f(v1);
                    *(__half2*)((__half*)Cv + (size_t)r * N + col) = __floats2half2_rn(v0, v1);
                } else if (epi == 3) {
                    *(__half2*)((__half*)Cv + (size_t)r * N + col) = __floats2half2_rn(v0, v1);
                } else {
                    if (epi == 2) {
                        float2 rr = *(const float2*)(res + (size_t)r * N + col);
                        v0 += rr.x; v1 += rr.y;
                    }
                    *(float2*)((float*)Cv + (size_t)r * N + col) = make_float2(v0, v1);
                }
            }
        }
    }
}

// ================= GEMM variant B: CTA 128x128, 2 CTAs/SM (N=768) =========
#define TA2     (128*PITCH)        // 10240
#define STAGE2  (2*TA2)            // 20480
#define GSMEM2  (2*STAGE2)         // 40960

__device__ __forceinline__ void load_chunk2(uint32_t sbase,
                                            const __half* pA, const __half* pB,
                                            int K, int tid) {
#pragma unroll
    for (int e = 0; e < 2; e++) {
        int idx = tid + e * 256;
        int r = idx >> 2, ch = idx & 3;
        uint32_t so = r * PITCH + ch * 16;
        size_t go = (size_t)r * K + ch * 8;
        cp16(sbase + so, pA + go);
        cp16(sbase + TA2 + so, pB + go);
    }
}

__global__ void __launch_bounds__(256, 2)
gemm_h2(const __half* __restrict__ A, const __half* __restrict__ Bt,
        const float* __restrict__ bias, const float* __restrict__ res,
        void* __restrict__ Cv, int N, int K, int epi) {
    extern __shared__ __align__(16) char smem[];
    uint32_t sb = smem_u32(smem);
    int tid = threadIdx.x, wid = tid >> 5, lane = tid & 31;
    int wm = wid >> 2, wn = wid & 3;       // warp tile: 64 x 32
    int m0 = blockIdx.y * 128, n0 = blockIdx.x * 128;

    const __half* pA = A  + (size_t)m0 * K;
    const __half* pB = Bt + (size_t)n0 * K;

    float acc[4][4][4] = {};

    const int NC = K / 32;
    load_chunk2(sb, pA, pB, K, tid);
    CP_COMMIT();

    int lrow = lane & 15;
    int lch  = (lane >> 4) * 16;

    for (int c = 0; c < NC; c++) {
        uint32_t st = sb + (c & 1) * STAGE2;
        if (c + 1 < NC) {
            load_chunk2(sb + ((c + 1) & 1) * STAGE2, pA + (c+1)*32, pB + (c+1)*32, K, tid);
            CP_COMMIT();
            CP_WAIT(1);
        } else {
            CP_WAIT(0);
        }
        __syncthreads();

#pragma unroll
        for (int ks = 0; ks < 2; ks++) {
            uint32_t ah[4][4], bh[2][4];
#pragma unroll
            for (int mi = 0; mi < 4; mi++) {
                uint32_t off = (uint32_t)(wm*64 + mi*16 + lrow) * PITCH + ks*32 + lch;
                ldm4(ah[mi], st + off);
            }
#pragma unroll
            for (int np = 0; np < 2; np++) {
                uint32_t off = (uint32_t)(wn*32 + np*16 + lrow) * PITCH + ks*32 + lch;
                ldm4(bh[np], st + TA2 + off);
            }
#pragma unroll
            for (int mi = 0; mi < 4; mi++)
#pragma unroll
                for (int ni = 0; ni < 4; ni++) {
                    int np = ni >> 1, sel = ni & 1;
                    mma16816(acc[mi][ni], ah[mi], bh[np][sel], bh[np][sel + 2]);
                }
        }
        __syncthreads();
    }

    int qrow = lane >> 2, qcol = (lane & 3) * 2;
#pragma unroll
    for (int mi = 0; mi < 4; mi++) {
#pragma unroll
        for (int ni = 0; ni < 4; ni++) {
            int row = m0 + wm*64 + mi*16 + qrow;
            int col = n0 + wn*32 + ni*8 + qcol;
            float b0 = bias[col], b1 = bias[col + 1];
#pragma unroll
            for (int hh = 0; hh < 2; hh++) {
                int r = row + hh * 8;
                float v0 = acc[mi][ni][hh*2 + 0] + b0;
                float v1 = acc[mi][ni][hh*2 + 1] + b1;
                if (epi == 1) {
                    v0 = gelu_f(v0); v1 = gelu_f(v1);
                    *(__half2*)((__half*)Cv + (size_t)r * N + col) = __floats2half2_rn(v0, v1);
                } else if (epi == 3) {
                    *(__half2*)((__half*)Cv + (size_t)r * N + col) = __floats2half2_rn(v0, v1);
                } else {
                    if (epi == 2) {
                        float2 rr = *(const float2*)(res + (size_t)r * N + col);
                        v0 += rr.x; v1 += rr.y;
                    }
                    *(float2*)((float*)Cv + (size_t)r * N + col) = make_float2(v0, v1);
                }
            }
        }
    }
}

// ---------------- reductions ----------------
__device__ __forceinline__ float warp_max(float v) {
#pragma unroll
    for (int o = 16; o; o >>= 1) v = fmaxf(v, __shfl_xor_sync(0xffffffffu, v, o));
    return v;
}
__device__ __forceinline__ float warp_sum(float v) {
#pragma unroll
    for (int o = 16; o; o >>= 1) v += __shfl_xor_sync(0xffffffffu, v, o);
    return v;
}

// ---------------- warp-per-row layernorm ----------------
__global__ void __launch_bounds__(256)
ln_kernel(const float* __restrict__ in, const float* __restrict__ g,
          const float* __restrict__ b, float* __restrict__ out,
          __half* __restrict__ outh) {
    int wid = threadIdx.x >> 5, lane = threadIdx.x & 31;
    int row = blockIdx.x * 8 + wid;
    const float* r = in + (size_t)row * D_;
    float vals[24];
    float s = 0.f, sq = 0.f;
#pragma unroll
    for (int i = 0; i < 24; i++) {
        vals[i] = r[lane + i * 32];
        s += vals[i]; sq += vals[i] * vals[i];
    }
    s = warp_sum(s); sq = warp_sum(sq);
    float mean = s * (1.0f / D_);
    float var = sq * (1.0f / D_) - mean * mean;
    float inv = rsqrtf(var + 1e-5f);
#pragma unroll
    for (int i = 0; i < 24; i++) {
        int d = lane + i * 32;
        float rr = (vals[i] - mean) * inv * g[d] + b[d];
        out[(size_t)row * D_ + d] = rr;
        outh[(size_t)row * D_ + d] = __float2half(rr);
    }
}

__global__ void __launch_bounds__(256)
embed_ln_kernel(const int* __restrict__ ids, const float* __restrict__ we,
                const float* __restrict__ pe, const float* __restrict__ te,
                const float* __restrict__ g, const float* __restrict__ b) {
    int wid = threadIdx.x >> 5, lane = threadIdx.x & 31;
    int row = blockIdx.x * 8 + wid;
    int s_ = row % S_;
    int id = ids[row];
    float vals[24];
    float s = 0.f, sq = 0.f;
#pragma unroll
    for (int i = 0; i < 24; i++) {
        int d = lane + i * 32;
        vals[i] = we[(size_t)id * D_ + d] + pe[(size_t)(s_ + 2) * D_ + d] + te[d];
        s += vals[i]; sq += vals[i] * vals[i];
    }
    s = warp_sum(s); sq = warp_sum(sq);
    float mean = s * (1.0f / D_);
    float var = sq * (1.0f / D_) - mean * mean;
    float inv = rsqrtf(var + 1e-5f);
#pragma unroll
    for (int i = 0; i < 24; i++) {
        int d = lane + i * 32;
        float rr = (vals[i] - mean) * inv * g[d] + b[d];
        g_x[(size_t)row * D_ + d] = rr;
        g_xh[(size_t)row * D_ + d] = __float2half(rr);
    }
}

// ---------------- tiled banded attention (reads fused qkv) ----------------
__global__ void __launch_bounds__(256)
attn_tile(const __half* __restrict__ qkv, const float* __restrict__ mask,
          __half* __restrict__ outh, int half) {
    __shared__ float qs[32][64];
    __shared__ float ks[32][65];
    __shared__ float vs[32][64];
    int tid = threadIdx.x, wid = tid >> 5, lane = tid & 31;
    int qt = blockIdx.x * 32;
    int bh = blockIdx.y;
    int b = bh / H_, h = bh % H_;
    const size_t base = (size_t)b * S_;

#pragma unroll
    for (int i = 0; i < 4; i++) {
        int idx = tid + i * 256;
        int r = idx >> 5, dp = idx & 31;
        float2 f = __half22float2(*(const __half2*)(qkv + (base + qt + r) * D3_ + h * HD_ + 2 * dp));
        qs[r][2*dp] = f.x * 0.125f; qs[r][2*dp+1] = f.y * 0.125f;
    }

    int q0 = wid * 4;
    float m[4], l[4], o0[4], o1[4];
#pragma unroll
    for (int i = 0; i < 4; i++) { m[i] = -1e30f; l[i] = 0.f; o0[i] = 0.f; o1[i] = 0.f; }

    int kt0 = (qt - half) >> 5; if (kt0 < 0) kt0 = 0;
    int kt1 = (qt + 31 + half) >> 5; if (kt1 > S_/32 - 1) kt1 = S_/32 - 1;

    for (int kt = kt0; kt <= kt1; kt++) {
        __syncthreads();
        int j0 = kt * 32;
#pragma unroll
        for (int i = 0; i < 4; i++) {
            int idx = tid + i * 256;
            int r = idx >> 5, dp = idx & 31;
            const __half* rowp = qkv + (base + j0 + r) * D3_ + h * HD_ + 2 * dp;
            float2 fk = __half22float2(*(const __half2*)(rowp + D_));
            float2 fv = __half22float2(*(const __half2*)(rowp + 2 * D_));
            ks[r][2*dp] = fk.x; ks[r][2*dp+1] = fk.y;
            vs[r][2*dp] = fv.x; vs[r][2*dp+1] = fv.y;
        }
        __syncthreads();

        int j = j0 + lane;
        float ka = (1.0f - mask[base + j]) * -1e9f;
        float sc[4] = {0.f, 0.f, 0.f, 0.f};
#pragma unroll
        for (int d = 0; d < 64; d++) {
            float kv = ks[lane][d];
            sc[0] += qs[q0 + 0][d] * kv;
            sc[1] += qs[q0 + 1][d] * kv;
            sc[2] += qs[q0 + 2][d] * kv;
            sc[3] += qs[q0 + 3][d] * kv;
        }
#pragma unroll
        for (int i = 0; i < 4; i++) {
            int qg = qt + q0 + i;
            bool valid = (j >= qg - half) && (j <= qg + half);
            float s = valid ? sc[i] + ka : -1e9f;
            float tmax = warp_max(s);
            float mn = fmaxf(m[i], tmax);
            float scale = __expf(m[i] - mn);
            float p = __expf(s - mn);
            float ls = warp_sum(p);
            m[i] = mn;
            l[i] = l[i] * scale + ls;
            o0[i] *= scale; o1[i] *= scale;
            if (ls != 0.f) {
#pragma unroll 8
                for (int kk = 0; kk < 32; kk++) {
                    float pk = __shfl_sync(0xffffffffu, p, kk);
                    float2 vv = ((const float2*)vs[kk])[lane];
                    o0[i] += pk * vv.x;
                    o1[i] += pk * vv.y;
                }
            }
        }
    }

#pragma unroll
    for (int i = 0; i < 4; i++) {
        int qg = qt + q0 + i;
        float inv = 1.0f / l[i];
        *(__half2*)(outh + (base + qg) * D_ + h * HD_ + 2 * lane) =
            __floats2half2_rn(o0[i] * inv, o1[i] * inv);
    }
}

// ---------------- top head ----------------
__global__ void top_kernel(const float* __restrict__ fts,
                           const float* __restrict__ Wtop,
                           const float* __restrict__ btop,
                           float* __restrict__ out) {
    int b = blockIdx.x;
    int lane = threadIdx.x & 31, wid = threadIdx.x >> 5;
    __shared__ float sw[8];
    const float* cls = g_x + (size_t)b * S_ * D_;
    float part = 0.f;
    for (int d = threadIdx.x; d < D_; d += 256) part += cls[d] * Wtop[d];
    part = warp_sum(part);
    if (lane == 0) sw[wid] = part;
    __syncthreads();
    if (threadIdx.x == 0) {
        float r = 0.f;
#pragma unroll
        for (int i = 0; i < 8; i++) r += sw[i];
        out[b] = r + fts[b] * Wtop[D_] + btop[0];
    }
}

// ---------------- host driver ----------------
extern "C" void kernel_launch(void* const* d_in, const int* in_sizes, int n_in,
                              void* d_out, int out_size) {
    const int*   ids  = (const int*)  d_in[0];
    const float* mask = (const float*)d_in[1];
    const float* fts  = (const float*)d_in[2];
    const float* we   = (const float*)d_in[3];
    const float* pe   = (const float*)d_in[4];
    const float* te   = (const float*)d_in[5];
    const float* ln_eg= (const float*)d_in[6];
    const float* ln_eb= (const float*)d_in[7];
    const float* Wq   = (const float*)d_in[8];
    const float* bq   = (const float*)d_in[9];
    const float* Wk   = (const float*)d_in[10];
    const float* bk   = (const float*)d_in[11];
    const float* Wv   = (const float*)d_in[12];
    const float* bv   = (const float*)d_in[13];
    const float* Wo   = (const float*)d_in[14];
    const float* bo   = (const float*)d_in[15];
    const float* ln1g = (const float*)d_in[16];
    const float* ln1b = (const float*)d_in[17];
    const float* W1   = (const float*)d_in[18];
    const float* b1   = (const float*)d_in[19];
    const float* W2   = (const float*)d_in[20];
    const float* b2   = (const float*)d_in[21];
    const float* ln2g = (const float*)d_in[22];
    const float* ln2b = (const float*)d_in[23];
    const float* Wtop = (const float*)d_in[24];
    const float* btop = (const float*)d_in[25];
    float* out = (float*)d_out;

    float *x, *tt, *bqkv;
    cudaGetSymbolAddress((void**)&x,  g_x);
    cudaGetSymbolAddress((void**)&tt, g_t);
    cudaGetSymbolAddress((void**)&bqkv, g_bqkv);

    __half *xh, *ah, *hh, *qkv, *wqkv, *wo, *w1, *w2;
    cudaGetSymbolAddress((void**)&xh, g_xh);
    cudaGetSymbolAddress((void**)&ah, g_ah);
    cudaGetSymbolAddress((void**)&hh, g_hh);
    cudaGetSymbolAddress((void**)&qkv, g_qkv);
    cudaGetSymbolAddress((void**)&wqkv, g_wqkv);
    cudaGetSymbolAddress((void**)&wo, g_wo);
    cudaGetSymbolAddress((void**)&w1, g_w1);
    cudaGetSymbolAddress((void**)&w2, g_w2);

    cudaFuncSetAttribute(gemm_h,  cudaFuncAttributeMaxDynamicSharedMemorySize, GSMEM);
    cudaFuncSetAttribute(gemm_h2, cudaFuncAttributeMaxDynamicSharedMemorySize, GSMEM2);

    static const int halves[L_] = {16,16,32,32,64,64,128,128,256,256,256,256};

    embed_ln_kernel<<<M_/8, 256>>>(ids, we, pe, te, ln_eg, ln_eb);

    // weight prep (batched over layers)
    dim3 tD(D_ / 32, D_ / 32, L_);
    dim3 t1(FF_ / 32, D_ / 32, L_);
    dim3 t2(D_ / 32, FF_ / 32, L_);
    size_t lsD = (size_t)D_ * D_, lsQKV = (size_t)D3_ * D_;
    ttrans_all<<<tD, 256>>>(Wq, wqkv + 0 * lsD, D_, D_, lsD, lsQKV);
    ttrans_all<<<tD, 256>>>(Wk, wqkv + 1 * lsD, D_, D_, lsD, lsQKV);
    ttrans_all<<<tD, 256>>>(Wv, wqkv + 2 * lsD, D_, D_, lsD, lsQKV);
    ttrans_all<<<tD, 256>>>(Wo, wo, D_, D_, lsD, lsD);
    ttrans_all<<<t1, 256>>>(W1, w1, D_, FF_, (size_t)D_*FF_, (size_t)FF_*D_);
    ttrans_all<<<t2, 256>>>(W2, w2, FF_, D_, (size_t)FF_*D_, (size_t)D_*FF_);
    bcat_kernel<<<(L_*D3_ + 255)/256, 256>>>(bq, bk, bv);

    dim3 gQKV(D3_ / 128, M_ / 256);  // (18, 16) = 288 CTAs (big tile)
    dim3 gD2(D_ / 128, M_ / 128);    // (6, 32) = 192 CTAs (small tile, 2/SM)
    dim3 gF(FF_ / 128, M_ / 256);    // (24, 16) = 384 CTAs (big tile)
    dim3 ga(S_ / 32, B_ * H_);       // (64, 24)

    for (int i = 0; i < L_; i++) {
        __half* lwqkv = wqkv + (size_t)i * lsQKV;
        __half* lwo = wo + (size_t)i * lsD;
        __half* lw1 = w1 + (size_t)i * FF_ * D_;
        __half* lw2 = w2 + (size_t)i * D_ * FF_;

        gemm_h<<<gQKV, 256, GSMEM>>>(xh, lwqkv, bqkv + (size_t)i*D3_, nullptr, qkv, D3_, D_, 3);

        attn_tile<<<ga, 256>>>(qkv, mask, ah, halves[i]);

        gemm_h2<<<gD2, 256, GSMEM2>>>(ah, lwo, bo + (size_t)i*D_, x, tt, D_, D_, 2);
        ln_kernel<<<M_/8, 256>>>(tt, ln1g + (size_t)i*D_, ln1b + (size_t)i*D_, x, xh);

        gemm_h<<<gF, 256, GSMEM>>>(xh, lw1, b1 + (size_t)i*FF_, nullptr, hh, FF_, D_, 1);

        gemm_h2<<<gD2, 256, GSMEM2>>>(hh, lw2, b2 + (size_t)i*D_, x, tt, D_, FF_, 2);
        ln_kernel<<<M_/8, 256>>>(tt, ln2g + (size_t)i*D_, ln2b + (size_t)i*D_, x, xh);
    }

    top_kernel<<<B_, 256>>>(fts, Wtop, btop, out);
}

// round 10
// speedup vs baseline: 1.0773x; 1.0773x over previous
#include <cuda_runtime.h>
#include <cuda_fp16.h>
#include <math.h>
#include <stdint.h>

#define B_ 2
#define S_ 2048
#define D_ 768
#define H_ 12
#define HD_ 64
#define FF_ 3072
#define L_ 12
#define M_ (B_*S_)   // 4096 rows
#define D3_ (3*D_)   // 2304
#define KS_ 3        // split-K factor for N=768 GEMMs

// ---------------- scratch (device globals; no allocation allowed) ----------
__device__ float g_x[M_*D_];
__device__ float g_p[KS_*M_*D_];                 // split-K partials

__device__ __align__(16) __half g_xh[M_*D_];     // fp16 x (GEMM A input)
__device__ __align__(16) __half g_ah[M_*D_];     // fp16 attention out
__device__ __align__(16) __half g_hh[M_*FF_];    // fp16 gelu out
__device__ __align__(16) __half g_qkv[M_*D3_];   // fused q|k|v rows
// transposed fp16 weights, ALL layers
__device__ __align__(16) __half g_wqkv[L_*D3_*D_];  // [L][2304][768]
__device__ __align__(16) __half g_wo[L_*D_*D_];
__device__ __align__(16) __half g_w1[L_*FF_*D_];    // N=3072,K=768
__device__ __align__(16) __half g_w2[L_*D_*FF_];    // N=768,K=3072
__device__ float g_bqkv[L_*D3_];

// ---------------- PTX helpers (base-target safe) ----------------
__device__ __forceinline__ uint32_t smem_u32(const void* p) {
    uint32_t a;
    asm("{ .reg .u64 t; cvta.to.shared.u64 t, %1; cvt.u32.u64 %0, t; }" : "=r"(a) : "l"(p));
    return a;
}
__device__ __forceinline__ void cp16(uint32_t s, const void* g) {
    asm volatile("cp.async.cg.shared.global [%0], [%1], 16;" :: "r"(s), "l"(g));
}
#define CP_COMMIT()  asm volatile("cp.async.commit_group;" ::: "memory")
#define CP_WAIT(n)   asm volatile("cp.async.wait_group %0;" :: "n"(n) : "memory")

__device__ __forceinline__ void ldm4(uint32_t* r, uint32_t addr) {
    asm volatile("ldmatrix.sync.aligned.m8n8.x4.shared.b16 {%0,%1,%2,%3}, [%4];"
        : "=r"(r[0]), "=r"(r[1]), "=r"(r[2]), "=r"(r[3]) : "r"(addr));
}
__device__ __forceinline__ void mma16816(float* c, const uint32_t* a, uint32_t b0, uint32_t b1) {
    asm volatile("mma.sync.aligned.m16n8k16.row.col.f32.f16.f16.f32 "
        "{%0,%1,%2,%3}, {%4,%5,%6,%7}, {%8,%9}, {%0,%1,%2,%3};"
        : "+f"(c[0]), "+f"(c[1]), "+f"(c[2]), "+f"(c[3])
        : "r"(a[0]), "r"(a[1]), "r"(a[2]), "r"(a[3]), "r"(b0), "r"(b1));
}

// ---------------- batched weight transpose -------------------------------
__global__ void ttrans_all(const float* __restrict__ W, __half* __restrict__ T,
                           int K, int N, size_t lsW, size_t lsT) {
    __shared__ float t[32][33];
    int li = blockIdx.z;
    const float* Wl = W + (size_t)li * lsW;
    __half* Tl = T + (size_t)li * lsT;
    int k0 = blockIdx.y * 32, n0 = blockIdx.x * 32;
    int tx = threadIdx.x & 31, ty = threadIdx.x >> 5;  // 32 x 8
#pragma unroll
    for (int i = 0; i < 4; i++)
        t[ty + i * 8][tx] = Wl[(size_t)(k0 + ty + i * 8) * N + n0 + tx];
    __syncthreads();
#pragma unroll
    for (int i = 0; i < 4; i++)
        Tl[(size_t)(n0 + ty + i * 8) * K + k0 + tx] = __float2half(t[tx][ty + i * 8]);
}

// concat biases: [L][D] x3 -> [L][3D]
__global__ void bcat_kernel(const float* __restrict__ bq, const float* __restrict__ bk,
                            const float* __restrict__ bv) {
    int i = blockIdx.x * blockDim.x + threadIdx.x;
    if (i >= L_ * D3_) return;
    int li = i / D3_, r = i % D3_;
    int sec = r / D_, d = r % D_;
    const float* src = sec == 0 ? bq : (sec == 1 ? bk : bv);
    g_bqkv[i] = src[li * D_ + d];
}

__device__ __forceinline__ float gelu_f(float c) {
    return 0.5f * c * (1.0f + erff(c * 0.70710678118654752f));
}

// ================= GEMM: CTA 256x128, 3-stage cp.async, split-K-aware =====
// A: [M,Kfull] fp16 K-major. B: [N,Kfull] fp16 K-major.
// Each CTA processes Keff of K starting at blockIdx.z*Keff.
// epi: 1 gelu (fp16 out), 3 bias-only (fp16 out), 4 split-K partial (f32, no bias)
#define PITCH   80
#define TA      (256*PITCH)        // 20480
#define TB      (128*PITCH)        // 10240
#define STAGE   (TA+TB)            // 30720
#define GSMEM   (3*STAGE)          // 92160

__device__ __forceinline__ void load_chunk(uint32_t sbase,
                                           const __half* pA, const __half* pB,
                                           int K, int tid) {
#pragma unroll
    for (int e = 0; e < 4; e++) {
        int idx = tid + e * 256;
        int r = idx >> 2, ch = idx & 3;
        cp16(sbase + r * PITCH + ch * 16, pA + (size_t)r * K + ch * 8);
    }
#pragma unroll
    for (int e = 0; e < 2; e++) {
        int idx = tid + e * 256;
        int r = idx >> 2, ch = idx & 3;
        cp16(sbase + TA + r * PITCH + ch * 16, pB + (size_t)r * K + ch * 8);
    }
}

__global__ void __launch_bounds__(256, 1)
gemm_h(const __half* __restrict__ A, const __half* __restrict__ Bt,
       const float* __restrict__ bias,
       void* __restrict__ Cv, int N, int Kfull, int Keff, int epi) {
    extern __shared__ __align__(16) char smem[];
    uint32_t sb = smem_u32(smem);
    int tid = threadIdx.x, wid = tid >> 5, lane = tid & 31;
    int wm = wid >> 1, wn = wid & 1;       // warp tile: 64 x 64
    int m0 = blockIdx.y * 256, n0 = blockIdx.x * 128;
    int z = blockIdx.z;

    const __half* pA = A  + (size_t)m0 * Kfull + (size_t)z * Keff;
    const __half* pB = Bt + (size_t)n0 * Kfull + (size_t)z * Keff;

    float acc[4][8][4] = {};

    const int NC = Keff / 32;
    load_chunk(sb, pA, pB, Kfull, tid);
    CP_COMMIT();
    if (NC > 1) {
        load_chunk(sb + STAGE, pA + 32, pB + 32, Kfull, tid);
        CP_COMMIT();
    }

    int lrow = lane & 15;
    int lch  = (lane >> 4) * 16;

    for (int c = 0; c < NC; c++) {
        if (c + 2 < NC) { CP_WAIT(1); } else { CP_WAIT(0); }
        __syncthreads();
        if (c + 2 < NC) {
            int ns = (c + 2) % 3;
            load_chunk(sb + ns * STAGE, pA + (c+2)*32, pB + (c+2)*32, Kfull, tid);
            CP_COMMIT();
        }
        uint32_t st = sb + (c % 3) * STAGE;

#pragma unroll
        for (int ks = 0; ks < 2; ks++) {
            uint32_t ah[4][4], bh[4][4];
#pragma unroll
            for (int mi = 0; mi < 4; mi++) {
                uint32_t off = (uint32_t)(wm*64 + mi*16 + lrow) * PITCH + ks*32 + lch;
                ldm4(ah[mi], st + off);
            }
#pragma unroll
            for (int np = 0; np < 4; np++) {
                uint32_t off = (uint32_t)(wn*64 + np*16 + lrow) * PITCH + ks*32 + lch;
                ldm4(bh[np], st + TA + off);
            }
#pragma unroll
            for (int mi = 0; mi < 4; mi++)
#pragma unroll
                for (int ni = 0; ni < 8; ni++) {
                    int np = ni >> 1, sel = ni & 1;
                    mma16816(acc[mi][ni], ah[mi], bh[np][sel], bh[np][sel + 2]);
                }
        }
    }

    int qrow = lane >> 2, qcol = (lane & 3) * 2;
#pragma unroll
    for (int mi = 0; mi < 4; mi++) {
#pragma unroll
        for (int ni = 0; ni < 8; ni++) {
            int row = m0 + wm*64 + mi*16 + qrow;
            int col = n0 + wn*64 + ni*8 + qcol;
#pragma unroll
            for (int hh = 0; hh < 2; hh++) {
                int r = row + hh * 8;
                float v0 = acc[mi][ni][hh*2 + 0];
                float v1 = acc[mi][ni][hh*2 + 1];
                if (epi == 4) {
                    *(float2*)((float*)Cv + (size_t)z * M_ * N + (size_t)r * N + col) =
                        make_float2(v0, v1);
                } else {
                    v0 += bias[col]; v1 += bias[col + 1];
                    if (epi == 1) { v0 = gelu_f(v0); v1 = gelu_f(v1); }
                    *(__half2*)((__half*)Cv + (size_t)r * N + col) = __floats2half2_rn(v0, v1);
                }
            }
        }
    }
}

// ---------------- reductions ----------------
__device__ __forceinline__ float warp_max(float v) {
#pragma unroll
    for (int o = 16; o; o >>= 1) v = fmaxf(v, __shfl_xor_sync(0xffffffffu, v, o));
    return v;
}
__device__ __forceinline__ float warp_sum(float v) {
#pragma unroll
    for (int o = 16; o; o >>= 1) v += __shfl_xor_sync(0xffffffffu, v, o);
    return v;
}

// ---------------- fused split-K reduce + residual + bias + LN -------------
// x_new = LN(x + P0 + P1 + P2 + bias); writes f32 + fp16 (in-place on x ok)
__global__ void __launch_bounds__(256)
ln3_kernel(const float* __restrict__ xres, const float* __restrict__ P,
           const float* __restrict__ bias, const float* __restrict__ g,
           const float* __restrict__ b, float* __restrict__ out,
           __half* __restrict__ outh) {
    int wid = threadIdx.x >> 5, lane = threadIdx.x & 31;
    int row = blockIdx.x * 8 + wid;
    const float* r0 = xres + (size_t)row * D_;
    const float* p0 = P + (size_t)row * D_;
    const float* p1 = P + (size_t)M_ * D_ + (size_t)row * D_;
    const float* p2 = P + 2 * (size_t)M_ * D_ + (size_t)row * D_;
    float vals[24];
    float s = 0.f, sq = 0.f;
#pragma unroll
    for (int i = 0; i < 24; i++) {
        int d = lane + i * 32;
        vals[i] = r0[d] + ((p0[d] + p1[d]) + p2[d]) + bias[d];
        s += vals[i]; sq += vals[i] * vals[i];
    }
    s = warp_sum(s); sq = warp_sum(sq);
    float mean = s * (1.0f / D_);
    float var = sq * (1.0f / D_) - mean * mean;
    float inv = rsqrtf(var + 1e-5f);
#pragma unroll
    for (int i = 0; i < 24; i++) {
        int d = lane + i * 32;
        float rr = (vals[i] - mean) * inv * g[d] + b[d];
        out[(size_t)row * D_ + d] = rr;
        outh[(size_t)row * D_ + d] = __float2half(rr);
    }
}

__global__ void __launch_bounds__(256)
embed_ln_kernel(const int* __restrict__ ids, const float* __restrict__ we,
                const float* __restrict__ pe, const float* __restrict__ te,
                const float* __restrict__ g, const float* __restrict__ b) {
    int wid = threadIdx.x >> 5, lane = threadIdx.x & 31;
    int row = blockIdx.x * 8 + wid;
    int s_ = row % S_;
    int id = ids[row];
    float vals[24];
    float s = 0.f, sq = 0.f;
#pragma unroll
    for (int i = 0; i < 24; i++) {
        int d = lane + i * 32;
        vals[i] = we[(size_t)id * D_ + d] + pe[(size_t)(s_ + 2) * D_ + d] + te[d];
        s += vals[i]; sq += vals[i] * vals[i];
    }
    s = warp_sum(s); sq = warp_sum(sq);
    float mean = s * (1.0f / D_);
    float var = sq * (1.0f / D_) - mean * mean;
    float inv = rsqrtf(var + 1e-5f);
#pragma unroll
    for (int i = 0; i < 24; i++) {
        int d = lane + i * 32;
        float rr = (vals[i] - mean) * inv * g[d] + b[d];
        g_x[(size_t)row * D_ + d] = rr;
        g_xh[(size_t)row * D_ + d] = __float2half(rr);
    }
}

// ---------------- tiled banded attention (reads fused qkv) ----------------
__global__ void __launch_bounds__(256)
attn_tile(const __half* __restrict__ qkv, const float* __restrict__ mask,
          __half* __restrict__ outh, int half) {
    __shared__ float qs[32][64];
    __shared__ float ks[32][65];
    __shared__ float vs[32][64];
    int tid = threadIdx.x, wid = tid >> 5, lane = tid & 31;
    int qt = blockIdx.x * 32;
    int bh = blockIdx.y;
    int b = bh / H_, h = bh % H_;
    const size_t base = (size_t)b * S_;

#pragma unroll
    for (int i = 0; i < 4; i++) {
        int idx = tid + i * 256;
        int r = idx >> 5, dp = idx & 31;
        float2 f = __half22float2(*(const __half2*)(qkv + (base + qt + r) * D3_ + h * HD_ + 2 * dp));
        qs[r][2*dp] = f.x * 0.125f; qs[r][2*dp+1] = f.y * 0.125f;
    }

    int q0 = wid * 4;
    float m[4], l[4], o0[4], o1[4];
#pragma unroll
    for (int i = 0; i < 4; i++) { m[i] = -1e30f; l[i] = 0.f; o0[i] = 0.f; o1[i] = 0.f; }

    int kt0 = (qt - half) >> 5; if (kt0 < 0) kt0 = 0;
    int kt1 = (qt + 31 + half) >> 5; if (kt1 > S_/32 - 1) kt1 = S_/32 - 1;

    for (int kt = kt0; kt <= kt1; kt++) {
        __syncthreads();
        int j0 = kt * 32;
#pragma unroll
        for (int i = 0; i < 4; i++) {
            int idx = tid + i * 256;
            int r = idx >> 5, dp = idx & 31;
            const __half* rowp = qkv + (base + j0 + r) * D3_ + h * HD_ + 2 * dp;
            float2 fk = __half22float2(*(const __half2*)(rowp + D_));
            float2 fv = __half22float2(*(const __half2*)(rowp + 2 * D_));
            ks[r][2*dp] = fk.x; ks[r][2*dp+1] = fk.y;
            vs[r][2*dp] = fv.x; vs[r][2*dp+1] = fv.y;
        }
        __syncthreads();

        int j = j0 + lane;
        float ka = (1.0f - mask[base + j]) * -1e9f;
        float sc[4] = {0.f, 0.f, 0.f, 0.f};
#pragma unroll
        for (int d = 0; d < 64; d++) {
            float kv = ks[lane][d];
            sc[0] += qs[q0 + 0][d] * kv;
            sc[1] += qs[q0 + 1][d] * kv;
            sc[2] += qs[q0 + 2][d] * kv;
            sc[3] += qs[q0 + 3][d] * kv;
        }
#pragma unroll
        for (int i = 0; i < 4; i++) {
            int qg = qt + q0 + i;
            bool valid = (j >= qg - half) && (j <= qg + half);
            float s = valid ? sc[i] + ka : -1e9f;
            float tmax = warp_max(s);
            float mn = fmaxf(m[i], tmax);
            float scale = __expf(m[i] - mn);
            float p = __expf(s - mn);
            float ls = warp_sum(p);
            m[i] = mn;
            l[i] = l[i] * scale + ls;
            o0[i] *= scale; o1[i] *= scale;
            if (ls != 0.f) {
#pragma unroll 8
                for (int kk = 0; kk < 32; kk++) {
                    float pk = __shfl_sync(0xffffffffu, p, kk);
                    float2 vv = ((const float2*)vs[kk])[lane];
                    o0[i] += pk * vv.x;
                    o1[i] += pk * vv.y;
                }
            }
        }
    }

#pragma unroll
    for (int i = 0; i < 4; i++) {
        int qg = qt + q0 + i;
        float inv = 1.0f / l[i];
        *(__half2*)(outh + (base + qg) * D_ + h * HD_ + 2 * lane) =
            __floats2half2_rn(o0[i] * inv, o1[i] * inv);
    }
}

// ---------------- top head ----------------
__global__ void top_kernel(const float* __restrict__ fts,
                           const float* __restrict__ Wtop,
                           const float* __restrict__ btop,
                           float* __restrict__ out) {
    int b = blockIdx.x;
    int lane = threadIdx.x & 31, wid = threadIdx.x >> 5;
    __shared__ float sw[8];
    const float* cls = g_x + (size_t)b * S_ * D_;
    float part = 0.f;
    for (int d = threadIdx.x; d < D_; d += 256) part += cls[d] * Wtop[d];
    part = warp_sum(part);
    if (lane == 0) sw[wid] = part;
    __syncthreads();
    if (threadIdx.x == 0) {
        float r = 0.f;
#pragma unroll
        for (int i = 0; i < 8; i++) r += sw[i];
        out[b] = r + fts[b] * Wtop[D_] + btop[0];
    }
}

// ---------------- host driver ----------------
extern "C" void kernel_launch(void* const* d_in, const int* in_sizes, int n_in,
                              void* d_out, int out_size) {
    const int*   ids  = (const int*)  d_in[0];
    const float* mask = (const float*)d_in[1];
    const float* fts  = (const float*)d_in[2];
    const float* we   = (const float*)d_in[3];
    const float* pe   = (const float*)d_in[4];
    const float* te   = (const float*)d_in[5];
    const float* ln_eg= (const float*)d_in[6];
    const float* ln_eb= (const float*)d_in[7];
    const float* Wq   = (const float*)d_in[8];
    const float* bq   = (const float*)d_in[9];
    const float* Wk   = (const float*)d_in[10];
    const float* bk   = (const float*)d_in[11];
    const float* Wv   = (const float*)d_in[12];
    const float* bv   = (const float*)d_in[13];
    const float* Wo   = (const float*)d_in[14];
    const float* bo   = (const float*)d_in[15];
    const float* ln1g = (const float*)d_in[16];
    const float* ln1b = (const float*)d_in[17];
    const float* W1   = (const float*)d_in[18];
    const float* b1   = (const float*)d_in[19];
    const float* W2   = (const float*)d_in[20];
    const float* b2   = (const float*)d_in[21];
    const float* ln2g = (const float*)d_in[22];
    const float* ln2b = (const float*)d_in[23];
    const float* Wtop = (const float*)d_in[24];
    const float* btop = (const float*)d_in[25];
    float* out = (float*)d_out;

    float *x, *pbuf, *bqkv;
    cudaGetSymbolAddress((void**)&x,  g_x);
    cudaGetSymbolAddress((void**)&pbuf, g_p);
    cudaGetSymbolAddress((void**)&bqkv, g_bqkv);

    __half *xh, *ah, *hh, *qkv, *wqkv, *wo, *w1, *w2;
    cudaGetSymbolAddress((void**)&xh, g_xh);
    cudaGetSymbolAddress((void**)&ah, g_ah);
    cudaGetSymbolAddress((void**)&hh, g_hh);
    cudaGetSymbolAddress((void**)&qkv, g_qkv);
    cudaGetSymbolAddress((void**)&wqkv, g_wqkv);
    cudaGetSymbolAddress((void**)&wo, g_wo);
    cudaGetSymbolAddress((void**)&w1, g_w1);
    cudaGetSymbolAddress((void**)&w2, g_w2);

    cudaFuncSetAttribute(gemm_h, cudaFuncAttributeMaxDynamicSharedMemorySize, GSMEM);

    static const int halves[L_] = {16,16,32,32,64,64,128,128,256,256,256,256};

    embed_ln_kernel<<<M_/8, 256>>>(ids, we, pe, te, ln_eg, ln_eb);

    // weight prep (batched over layers)
    dim3 tD(D_ / 32, D_ / 32, L_);
    dim3 t1(FF_ / 32, D_ / 32, L_);
    dim3 t2(D_ / 32, FF_ / 32, L_);
    size_t lsD = (size_t)D_ * D_, lsQKV = (size_t)D3_ * D_;
    ttrans_all<<<tD, 256>>>(Wq, wqkv + 0 * lsD, D_, D_, lsD, lsQKV);
    ttrans_all<<<tD, 256>>>(Wk, wqkv + 1 * lsD, D_, D_, lsD, lsQKV);
    ttrans_all<<<tD, 256>>>(Wv, wqkv + 2 * lsD, D_, D_, lsD, lsQKV);
    ttrans_all<<<tD, 256>>>(Wo, wo, D_, D_, lsD, lsD);
    ttrans_all<<<t1, 256>>>(W1, w1, D_, FF_, (size_t)D_*FF_, (size_t)FF_*D_);
    ttrans_all<<<t2, 256>>>(W2, w2, FF_, D_, (size_t)FF_*D_, (size_t)D_*FF_);
    bcat_kernel<<<(L_*D3_ + 255)/256, 256>>>(bq, bk, bv);

    dim3 gQKV(D3_ / 128, M_ / 256, 1);   // (18, 16) = 288 CTAs
    dim3 gF(FF_ / 128, M_ / 256, 1);     // (24, 16) = 384 CTAs
    dim3 gSK(D_ / 128, M_ / 256, KS_);   // (6, 16, 3) = 288 CTAs split-K
    dim3 ga(S_ / 32, B_ * H_);           // (64, 24)

    for (int i = 0; i < L_; i++) {
        __half* lwqkv = wqkv + (size_t)i * lsQKV;
        __half* lwo = wo + (size_t)i * lsD;
        __half* lw1 = w1 + (size_t)i * FF_ * D_;
        __half* lw2 = w2 + (size_t)i * D_ * FF_;

        gemm_h<<<gQKV, 256, GSMEM>>>(xh, lwqkv, bqkv + (size_t)i*D3_, qkv, D3_, D_, D_, 3);

        attn_tile<<<ga, 256>>>(qkv, mask, ah, halves[i]);

        // Wo: split-K partials + fused reduce/residual/LN
        gemm_h<<<gSK, 256, GSMEM>>>(ah, lwo, nullptr, pbuf, D_, D_, D_ / KS_, 4);
        ln3_kernel<<<M_/8, 256>>>(x, pbuf, bo + (size_t)i*D_,
                                  ln1g + (size_t)i*D_, ln1b + (size_t)i*D_, x, xh);

        gemm_h<<<gF, 256, GSMEM>>>(xh, lw1, b1 + (size_t)i*FF_, hh, FF_, D_, D_, 1);

        // W2: split-K partials + fused reduce/residual/LN
        gemm_h<<<gSK, 256, GSMEM>>>(hh, lw2, nullptr, pbuf, D_, FF_, FF_ / KS_, 4);
        ln3_kernel<<<M_/8, 256>>>(x, pbuf, b2 + (size_t)i*D_,
                                  ln2g + (size_t)i*D_, ln2b + (size_t)i*D_, x, xh);
    }

    top_kernel<<<B_, 256>>>(fts, Wtop, btop, out);
}

// round 11
// speedup vs baseline: 1.7748x; 1.6475x over previous
#include <cuda_runtime.h>
#include <cuda_fp16.h>
#include <math.h>
#include <stdint.h>

#define B_ 2
#define S_ 2048
#define D_ 768
#define H_ 12
#define HD_ 64
#define FF_ 3072
#define L_ 12
#define M_ (B_*S_)   // 4096 rows
#define D3_ (3*D_)   // 2304
#define KS_ 3        // split-K factor for N=768 GEMMs

// ---------------- scratch (device globals; no allocation allowed) ----------
__device__ float g_x[M_*D_];
__device__ float g_p[KS_*M_*D_];                 // split-K partials

__device__ __align__(16) __half g_xh[M_*D_];     // fp16 x (GEMM A input)
__device__ __align__(16) __half g_ah[M_*D_];     // fp16 attention out
__device__ __align__(16) __half g_hh[M_*FF_];    // fp16 gelu out
__device__ __align__(16) __half g_qkv[M_*D3_];   // fused q|k|v rows
// transposed fp16 weights, ALL layers
__device__ __align__(16) __half g_wqkv[L_*D3_*D_];  // [L][2304][768]
__device__ __align__(16) __half g_wo[L_*D_*D_];
__device__ __align__(16) __half g_w1[L_*FF_*D_];    // N=3072,K=768
__device__ __align__(16) __half g_w2[L_*D_*FF_];    // N=768,K=3072
__device__ float g_bqkv[L_*D3_];

// ---------------- PTX helpers (base-target safe) ----------------
__device__ __forceinline__ uint32_t smem_u32(const void* p) {
    uint32_t a;
    asm("{ .reg .u64 t; cvta.to.shared.u64 t, %1; cvt.u32.u64 %0, t; }" : "=r"(a) : "l"(p));
    return a;
}
__device__ __forceinline__ void cp16(uint32_t s, const void* g) {
    asm volatile("cp.async.cg.shared.global [%0], [%1], 16;" :: "r"(s), "l"(g));
}
#define CP_COMMIT()  asm volatile("cp.async.commit_group;" ::: "memory")
#define CP_WAIT(n)   asm volatile("cp.async.wait_group %0;" :: "n"(n) : "memory")

__device__ __forceinline__ void ldm4(uint32_t* r, uint32_t addr) {
    asm volatile("ldmatrix.sync.aligned.m8n8.x4.shared.b16 {%0,%1,%2,%3}, [%4];"
        : "=r"(r[0]), "=r"(r[1]), "=r"(r[2]), "=r"(r[3]) : "r"(addr));
}
__device__ __forceinline__ void ldm4t(uint32_t* r, uint32_t addr) {
    asm volatile("ldmatrix.sync.aligned.m8n8.x4.trans.shared.b16 {%0,%1,%2,%3}, [%4];"
        : "=r"(r[0]), "=r"(r[1]), "=r"(r[2]), "=r"(r[3]) : "r"(addr));
}
__device__ __forceinline__ void mma16816(float* c, const uint32_t* a, uint32_t b0, uint32_t b1) {
    asm volatile("mma.sync.aligned.m16n8k16.row.col.f32.f16.f16.f32 "
        "{%0,%1,%2,%3}, {%4,%5,%6,%7}, {%8,%9}, {%0,%1,%2,%3};"
        : "+f"(c[0]), "+f"(c[1]), "+f"(c[2]), "+f"(c[3])
        : "r"(a[0]), "r"(a[1]), "r"(a[2]), "r"(a[3]), "r"(b0), "r"(b1));
}
__device__ __forceinline__ uint32_t packh2(float a, float b) {
    __half2 h = __floats2half2_rn(a, b);
    return *reinterpret_cast<uint32_t*>(&h);
}

// ---------------- batched weight transpose -------------------------------
__global__ void ttrans_all(const float* __restrict__ W, __half* __restrict__ T,
                           int K, int N, size_t lsW, size_t lsT) {
    __shared__ float t[32][33];
    int li = blockIdx.z;
    const float* Wl = W + (size_t)li * lsW;
    __half* Tl = T + (size_t)li * lsT;
    int k0 = blockIdx.y * 32, n0 = blockIdx.x * 32;
    int tx = threadIdx.x & 31, ty = threadIdx.x >> 5;  // 32 x 8
#pragma unroll
    for (int i = 0; i < 4; i++)
        t[ty + i * 8][tx] = Wl[(size_t)(k0 + ty + i * 8) * N + n0 + tx];
    __syncthreads();
#pragma unroll
    for (int i = 0; i < 4; i++)
        Tl[(size_t)(n0 + ty + i * 8) * K + k0 + tx] = __float2half(t[tx][ty + i * 8]);
}

// concat biases: [L][D] x3 -> [L][3D]
__global__ void bcat_kernel(const float* __restrict__ bq, const float* __restrict__ bk,
                            const float* __restrict__ bv) {
    int i = blockIdx.x * blockDim.x + threadIdx.x;
    if (i >= L_ * D3_) return;
    int li = i / D3_, r = i % D3_;
    int sec = r / D_, d = r % D_;
    const float* src = sec == 0 ? bq : (sec == 1 ? bk : bv);
    g_bqkv[i] = src[li * D_ + d];
}

__device__ __forceinline__ float gelu_f(float c) {
    return 0.5f * c * (1.0f + erff(c * 0.70710678118654752f));
}

// ================= GEMM: CTA 256x128, 3-stage cp.async, split-K-aware =====
#define PITCH   80
#define TA      (256*PITCH)        // 20480
#define TB      (128*PITCH)        // 10240
#define STAGE   (TA+TB)            // 30720
#define GSMEM   (3*STAGE)          // 92160

__device__ __forceinline__ void load_chunk(uint32_t sbase,
                                           const __half* pA, const __half* pB,
                                           int K, int tid) {
#pragma unroll
    for (int e = 0; e < 4; e++) {
        int idx = tid + e * 256;
        int r = idx >> 2, ch = idx & 3;
        cp16(sbase + r * PITCH + ch * 16, pA + (size_t)r * K + ch * 8);
    }
#pragma unroll
    for (int e = 0; e < 2; e++) {
        int idx = tid + e * 256;
        int r = idx >> 2, ch = idx & 3;
        cp16(sbase + TA + r * PITCH + ch * 16, pB + (size_t)r * K + ch * 8);
    }
}

__global__ void __launch_bounds__(256, 1)
gemm_h(const __half* __restrict__ A, const __half* __restrict__ Bt,
       const float* __restrict__ bias,
       void* __restrict__ Cv, int N, int Kfull, int Keff, int epi) {
    extern __shared__ __align__(16) char smem[];
    uint32_t sb = smem_u32(smem);
    int tid = threadIdx.x, wid = tid >> 5, lane = tid & 31;
    int wm = wid >> 1, wn = wid & 1;       // warp tile: 64 x 64
    int m0 = blockIdx.y * 256, n0 = blockIdx.x * 128;
    int z = blockIdx.z;

    const __half* pA = A  + (size_t)m0 * Kfull + (size_t)z * Keff;
    const __half* pB = Bt + (size_t)n0 * Kfull + (size_t)z * Keff;

    float acc[4][8][4] = {};

    const int NC = Keff / 32;
    load_chunk(sb, pA, pB, Kfull, tid);
    CP_COMMIT();
    if (NC > 1) {
        load_chunk(sb + STAGE, pA + 32, pB + 32, Kfull, tid);
        CP_COMMIT();
    }

    int lrow = lane & 15;
    int lch  = (lane >> 4) * 16;

    for (int c = 0; c < NC; c++) {
        if (c + 2 < NC) { CP_WAIT(1); } else { CP_WAIT(0); }
        __syncthreads();
        if (c + 2 < NC) {
            int ns = (c + 2) % 3;
            load_chunk(sb + ns * STAGE, pA + (c+2)*32, pB + (c+2)*32, Kfull, tid);
            CP_COMMIT();
        }
        uint32_t st = sb + (c % 3) * STAGE;

#pragma unroll
        for (int ks = 0; ks < 2; ks++) {
            uint32_t ah[4][4], bh[4][4];
#pragma unroll
            for (int mi = 0; mi < 4; mi++) {
                uint32_t off = (uint32_t)(wm*64 + mi*16 + lrow) * PITCH + ks*32 + lch;
                ldm4(ah[mi], st + off);
            }
#pragma unroll
            for (int np = 0; np < 4; np++) {
                uint32_t off = (uint32_t)(wn*64 + np*16 + lrow) * PITCH + ks*32 + lch;
                ldm4(bh[np], st + TA + off);
            }
#pragma unroll
            for (int mi = 0; mi < 4; mi++)
#pragma unroll
                for (int ni = 0; ni < 8; ni++) {
                    int np = ni >> 1, sel = ni & 1;
                    mma16816(acc[mi][ni], ah[mi], bh[np][sel], bh[np][sel + 2]);
                }
        }
    }

    int qrow = lane >> 2, qcol = (lane & 3) * 2;
#pragma unroll
    for (int mi = 0; mi < 4; mi++) {
#pragma unroll
        for (int ni = 0; ni < 8; ni++) {
            int row = m0 + wm*64 + mi*16 + qrow;
            int col = n0 + wn*64 + ni*8 + qcol;
#pragma unroll
            for (int hh = 0; hh < 2; hh++) {
                int r = row + hh * 8;
                float v0 = acc[mi][ni][hh*2 + 0];
                float v1 = acc[mi][ni][hh*2 + 1];
                if (epi == 4) {
                    *(float2*)((float*)Cv + (size_t)z * M_ * N + (size_t)r * N + col) =
                        make_float2(v0, v1);
                } else {
                    v0 += bias[col]; v1 += bias[col + 1];
                    if (epi == 1) { v0 = gelu_f(v0); v1 = gelu_f(v1); }
                    *(__half2*)((__half*)Cv + (size_t)r * N + col) = __floats2half2_rn(v0, v1);
                }
            }
        }
    }
}

// ---------------- reductions ----------------
__device__ __forceinline__ float warp_sum(float v) {
#pragma unroll
    for (int o = 16; o; o >>= 1) v += __shfl_xor_sync(0xffffffffu, v, o);
    return v;
}

// ---------------- fused split-K reduce + residual + bias + LN -------------
__global__ void __launch_bounds__(256)
ln3_kernel(const float* __restrict__ xres, const float* __restrict__ P,
           const float* __restrict__ bias, const float* __restrict__ g,
           const float* __restrict__ b, float* __restrict__ out,
           __half* __restrict__ outh) {
    int wid = threadIdx.x >> 5, lane = threadIdx.x & 31;
    int row = blockIdx.x * 8 + wid;
    const float* r0 = xres + (size_t)row * D_;
    const float* p0 = P + (size_t)row * D_;
    const float* p1 = P + (size_t)M_ * D_ + (size_t)row * D_;
    const float* p2 = P + 2 * (size_t)M_ * D_ + (size_t)row * D_;
    float vals[24];
    float s = 0.f, sq = 0.f;
#pragma unroll
    for (int i = 0; i < 24; i++) {
        int d = lane + i * 32;
        vals[i] = r0[d] + ((p0[d] + p1[d]) + p2[d]) + bias[d];
        s += vals[i]; sq += vals[i] * vals[i];
    }
    s = warp_sum(s); sq = warp_sum(sq);
    float mean = s * (1.0f / D_);
    float var = sq * (1.0f / D_) - mean * mean;
    float inv = rsqrtf(var + 1e-5f);
#pragma unroll
    for (int i = 0; i < 24; i++) {
        int d = lane + i * 32;
        float rr = (vals[i] - mean) * inv * g[d] + b[d];
        out[(size_t)row * D_ + d] = rr;
        outh[(size_t)row * D_ + d] = __float2half(rr);
    }
}

__global__ void __launch_bounds__(256)
embed_ln_kernel(const int* __restrict__ ids, const float* __restrict__ we,
                const float* __restrict__ pe, const float* __restrict__ te,
                const float* __restrict__ g, const float* __restrict__ b) {
    int wid = threadIdx.x >> 5, lane = threadIdx.x & 31;
    int row = blockIdx.x * 8 + wid;
    int s_ = row % S_;
    int id = ids[row];
    float vals[24];
    float s = 0.f, sq = 0.f;
#pragma unroll
    for (int i = 0; i < 24; i++) {
        int d = lane + i * 32;
        vals[i] = we[(size_t)id * D_ + d] + pe[(size_t)(s_ + 2) * D_ + d] + te[d];
        s += vals[i]; sq += vals[i] * vals[i];
    }
    s = warp_sum(s); sq = warp_sum(sq);
    float mean = s * (1.0f / D_);
    float var = sq * (1.0f / D_) - mean * mean;
    float inv = rsqrtf(var + 1e-5f);
#pragma unroll
    for (int i = 0; i < 24; i++) {
        int d = lane + i * 32;
        float rr = (vals[i] - mean) * inv * g[d] + b[d];
        g_x[(size_t)row * D_ + d] = rr;
        g_xh[(size_t)row * D_ + d] = __float2half(rr);
    }
}

// ---------------- tensor-core banded attention ----------------
// block = 128 queries x (b,h); 8 warps, warp owns 16 query rows.
// S = Q K^T via mma (f32 accum), online softmax in registers,
// P(fp16) V via mma with ldmatrix.trans for V fragments.
__global__ void __launch_bounds__(256)
attn_mma(const __half* __restrict__ qkv, const float* __restrict__ mask,
         __half* __restrict__ outh, int half) {
    __shared__ __align__(16) __half qs[128][72];
    __shared__ __align__(16) __half ks[32][72];
    __shared__ __align__(16) __half vs[32][72];
    __shared__ float kadd[32];
    int tid = threadIdx.x, wid = tid >> 5, lane = tid & 31;
    int qt = blockIdx.x * 128;
    int bh = blockIdx.y;
    int b = bh / H_, h = bh % H_;
    const size_t base = (size_t)b * S_;

    // load Q tile: 128 rows x 64 halves (1024 uint4)
#pragma unroll
    for (int i = 0; i < 4; i++) {
        int idx = tid + i * 256;
        int r = idx >> 3, seg = idx & 7;
        *(uint4*)&qs[r][seg * 8] =
            *(const uint4*)(qkv + (base + qt + r) * D3_ + h * HD_ + seg * 8);
    }
    __syncthreads();

    // persistent Q A-frags (16 regs)
    uint32_t qa[4][4];
    {
        int r = wid * 16 + (lane & 15);
        int cc = (lane >> 4) * 8;
#pragma unroll
        for (int k4 = 0; k4 < 4; k4++)
            ldm4(qa[k4], smem_u32(&qs[r][k4 * 16 + cc]));
    }

    float m0 = -1e30f, m1 = -1e30f, l0 = 0.f, l1 = 0.f;
    float oa[8][4];
#pragma unroll
    for (int t = 0; t < 8; t++) { oa[t][0]=0.f; oa[t][1]=0.f; oa[t][2]=0.f; oa[t][3]=0.f; }

    int qg0 = qt + wid * 16 + (lane >> 2);
    int qg1 = qg0 + 8;
    int kcol = (lane & 3) * 2;

    int kt0 = qt - half; if (kt0 < 0) kt0 = 0; kt0 >>= 5;
    int kt1 = qt + 127 + half; if (kt1 > S_ - 1) kt1 = S_ - 1; kt1 >>= 5;

    for (int kt = kt0; kt <= kt1; kt++) {
        int j0 = kt * 32;
        __syncthreads();
        {
            int r = tid >> 3, seg = tid & 7;
            const __half* rp = qkv + (base + j0 + r) * D3_ + h * HD_ + seg * 8;
            *(uint4*)&ks[r][seg * 8] = *(const uint4*)(rp + D_);
            *(uint4*)&vs[r][seg * 8] = *(const uint4*)(rp + 2 * D_);
        }
        if (tid < 32) kadd[tid] = (1.0f - mask[base + j0 + tid]) * -1e9f;
        __syncthreads();

        // S = Q @ K^T (keys are [key][dim] K-major -> standard B operand)
        float sa[4][4] = {};
        {
            int rr = lane & 15, cc = (lane >> 4) * 8;
#pragma unroll
            for (int k4 = 0; k4 < 4; k4++) {
                uint32_t kb0[4], kb1[4];
                ldm4(kb0, smem_u32(&ks[rr][k4 * 16 + cc]));
                ldm4(kb1, smem_u32(&ks[16 + rr][k4 * 16 + cc]));
                mma16816(sa[0], qa[k4], kb0[0], kb0[2]);
                mma16816(sa[1], qa[k4], kb0[1], kb0[3]);
                mma16816(sa[2], qa[k4], kb1[0], kb1[2]);
                mma16816(sa[3], qa[k4], kb1[1], kb1[3]);
            }
        }

        // mask + band + online softmax
        float mt0 = -1e30f, mt1 = -1e30f;
#pragma unroll
        for (int nt = 0; nt < 4; nt++) {
            float2 ka2 = *(float2*)&kadd[nt * 8 + kcol];
#pragma unroll
            for (int e = 0; e < 2; e++) {
                int key = j0 + nt * 8 + kcol + e;
                float ka = e ? ka2.y : ka2.x;
                float s0 = sa[nt][e] * 0.125f + ka;
                float s1 = sa[nt][2 + e] * 0.125f + ka;
                if (key < qg0 - half || key > qg0 + half) s0 = -1e9f;
                if (key < qg1 - half || key > qg1 + half) s1 = -1e9f;
                sa[nt][e] = s0; sa[nt][2 + e] = s1;
                mt0 = fmaxf(mt0, s0); mt1 = fmaxf(mt1, s1);
            }
        }
        mt0 = fmaxf(mt0, __shfl_xor_sync(0xffffffffu, mt0, 1));
        mt0 = fmaxf(mt0, __shfl_xor_sync(0xffffffffu, mt0, 2));
        mt1 = fmaxf(mt1, __shfl_xor_sync(0xffffffffu, mt1, 1));
        mt1 = fmaxf(mt1, __shfl_xor_sync(0xffffffffu, mt1, 2));
        float mn0 = fmaxf(m0, mt0), mn1 = fmaxf(m1, mt1);
        float sc0 = __expf(m0 - mn0), sc1 = __expf(m1 - mn1);
        m0 = mn0; m1 = mn1;

        float ls0 = 0.f, ls1 = 0.f;
        uint32_t pa[2][4];
#pragma unroll
        for (int nt = 0; nt < 4; nt++) {
            float p0 = __expf(sa[nt][0] - mn0);
            float p1 = __expf(sa[nt][1] - mn0);
            float p2 = __expf(sa[nt][2] - mn1);
            float p3 = __expf(sa[nt][3] - mn1);
            ls0 += p0 + p1; ls1 += p2 + p3;
            int kst = nt >> 1, hi = (nt & 1) * 2;
            pa[kst][hi + 0] = packh2(p0, p1);
            pa[kst][hi + 1] = packh2(p2, p3);
        }
        ls0 += __shfl_xor_sync(0xffffffffu, ls0, 1);
        ls0 += __shfl_xor_sync(0xffffffffu, ls0, 2);
        ls1 += __shfl_xor_sync(0xffffffffu, ls1, 1);
        ls1 += __shfl_xor_sync(0xffffffffu, ls1, 2);
        l0 = l0 * sc0 + ls0; l1 = l1 * sc1 + ls1;

#pragma unroll
        for (int t = 0; t < 8; t++) {
            oa[t][0] *= sc0; oa[t][1] *= sc0; oa[t][2] *= sc1; oa[t][3] *= sc1;
        }

        // O += P @ V (V frags via ldmatrix.trans on [key][dim] tile)
        {
            int rr = lane & 15, cc = (lane >> 4) * 8;
#pragma unroll
            for (int kst = 0; kst < 2; kst++) {
#pragma unroll
                for (int dg = 0; dg < 4; dg++) {
                    uint32_t vb[4];
                    ldm4t(vb, smem_u32(&vs[kst * 16 + rr][dg * 16 + cc]));
                    mma16816(oa[dg * 2],     pa[kst], vb[0], vb[1]);
                    mma16816(oa[dg * 2 + 1], pa[kst], vb[2], vb[3]);
                }
            }
        }
    }

    float inv0 = 1.0f / l0, inv1 = 1.0f / l1;
    __half* op0 = outh + (base + qg0) * D_ + h * HD_;
    __half* op1 = outh + (base + qg1) * D_ + h * HD_;
#pragma unroll
    for (int t = 0; t < 8; t++) {
        int dim = t * 8 + kcol;
        *(__half2*)(op0 + dim) = __floats2half2_rn(oa[t][0] * inv0, oa[t][1] * inv0);
        *(__half2*)(op1 + dim) = __floats2half2_rn(oa[t][2] * inv1, oa[t][3] * inv1);
    }
}

// ---------------- top head ----------------
__global__ void top_kernel(const float* __restrict__ fts,
                           const float* __restrict__ Wtop,
                           const float* __restrict__ btop,
                           float* __restrict__ out) {
    int b = blockIdx.x;
    int lane = threadIdx.x & 31, wid = threadIdx.x >> 5;
    __shared__ float sw[8];
    const float* cls = g_x + (size_t)b * S_ * D_;
    float part = 0.f;
    for (int d = threadIdx.x; d < D_; d += 256) part += cls[d] * Wtop[d];
    part = warp_sum(part);
    if (lane == 0) sw[wid] = part;
    __syncthreads();
    if (threadIdx.x == 0) {
        float r = 0.f;
#pragma unroll
        for (int i = 0; i < 8; i++) r += sw[i];
        out[b] = r + fts[b] * Wtop[D_] + btop[0];
    }
}

// ---------------- host driver ----------------
extern "C" void kernel_launch(void* const* d_in, const int* in_sizes, int n_in,
                              void* d_out, int out_size) {
    const int*   ids  = (const int*)  d_in[0];
    const float* mask = (const float*)d_in[1];
    const float* fts  = (const float*)d_in[2];
    const float* we   = (const float*)d_in[3];
    const float* pe   = (const float*)d_in[4];
    const float* te   = (const float*)d_in[5];
    const float* ln_eg= (const float*)d_in[6];
    const float* ln_eb= (const float*)d_in[7];
    const float* Wq   = (const float*)d_in[8];
    const float* bq   = (const float*)d_in[9];
    const float* Wk   = (const float*)d_in[10];
    const float* bk   = (const float*)d_in[11];
    const float* Wv   = (const float*)d_in[12];
    const float* bv   = (const float*)d_in[13];
    const float* Wo   = (const float*)d_in[14];
    const float* bo   = (const float*)d_in[15];
    const float* ln1g = (const float*)d_in[16];
    const float* ln1b = (const float*)d_in[17];
    const float* W1   = (const float*)d_in[18];
    const float* b1   = (const float*)d_in[19];
    const float* W2   = (const float*)d_in[20];
    const float* b2   = (const float*)d_in[21];
    const float* ln2g = (const float*)d_in[22];
    const float* ln2b = (const float*)d_in[23];
    const float* Wtop = (const float*)d_in[24];
    const float* btop = (const float*)d_in[25];
    float* out = (float*)d_out;

    float *x, *pbuf, *bqkv;
    cudaGetSymbolAddress((void**)&x,  g_x);
    cudaGetSymbolAddress((void**)&pbuf, g_p);
    cudaGetSymbolAddress((void**)&bqkv, g_bqkv);

    __half *xh, *ah, *hh, *qkv, *wqkv, *wo, *w1, *w2;
    cudaGetSymbolAddress((void**)&xh, g_xh);
    cudaGetSymbolAddress((void**)&ah, g_ah);
    cudaGetSymbolAddress((void**)&hh, g_hh);
    cudaGetSymbolAddress((void**)&qkv, g_qkv);
    cudaGetSymbolAddress((void**)&wqkv, g_wqkv);
    cudaGetSymbolAddress((void**)&wo, g_wo);
    cudaGetSymbolAddress((void**)&w1, g_w1);
    cudaGetSymbolAddress((void**)&w2, g_w2);

    cudaFuncSetAttribute(gemm_h, cudaFuncAttributeMaxDynamicSharedMemorySize, GSMEM);

    static const int halves[L_] = {16,16,32,32,64,64,128,128,256,256,256,256};

    embed_ln_kernel<<<M_/8, 256>>>(ids, we, pe, te, ln_eg, ln_eb);

    // weight prep (batched over layers)
    dim3 tD(D_ / 32, D_ / 32, L_);
    dim3 t1(FF_ / 32, D_ / 32, L_);
    dim3 t2(D_ / 32, FF_ / 32, L_);
    size_t lsD = (size_t)D_ * D_, lsQKV = (size_t)D3_ * D_;
    ttrans_all<<<tD, 256>>>(Wq, wqkv + 0 * lsD, D_, D_, lsD, lsQKV);
    ttrans_all<<<tD, 256>>>(Wk, wqkv + 1 * lsD, D_, D_, lsD, lsQKV);
    ttrans_all<<<tD, 256>>>(Wv, wqkv + 2 * lsD, D_, D_, lsD, lsQKV);
    ttrans_all<<<tD, 256>>>(Wo, wo, D_, D_, lsD, lsD);
    ttrans_all<<<t1, 256>>>(W1, w1, D_, FF_, (size_t)D_*FF_, (size_t)FF_*D_);
    ttrans_all<<<t2, 256>>>(W2, w2, FF_, D_, (size_t)FF_*D_, (size_t)D_*FF_);
    bcat_kernel<<<(L_*D3_ + 255)/256, 256>>>(bq, bk, bv);

    dim3 gQKV(D3_ / 128, M_ / 256, 1);   // (18, 16) = 288 CTAs
    dim3 gF(FF_ / 128, M_ / 256, 1);     // (24, 16) = 384 CTAs
    dim3 gSK(D_ / 128, M_ / 256, KS_);   // (6, 16, 3) = 288 CTAs split-K
    dim3 ga(S_ / 128, B_ * H_);          // (16, 24) = 384 blocks

    for (int i = 0; i < L_; i++) {
        __half* lwqkv = wqkv + (size_t)i * lsQKV;
        __half* lwo = wo + (size_t)i * lsD;
        __half* lw1 = w1 + (size_t)i * FF_ * D_;
        __half* lw2 = w2 + (size_t)i * D_ * FF_;

        gemm_h<<<gQKV, 256, GSMEM>>>(xh, lwqkv, bqkv + (size_t)i*D3_, qkv, D3_, D_, D_, 3);

        attn_mma<<<ga, 256>>>(qkv, mask, ah, halves[i]);

        // Wo: split-K partials + fused reduce/residual/LN
        gemm_h<<<gSK, 256, GSMEM>>>(ah, lwo, nullptr, pbuf, D_, D_, D_ / KS_, 4);
        ln3_kernel<<<M_/8, 256>>>(x, pbuf, bo + (size_t)i*D_,
                                  ln1g + (size_t)i*D_, ln1b + (size_t)i*D_, x, xh);

        gemm_h<<<gF, 256, GSMEM>>>(xh, lw1, b1 + (size_t)i*FF_, hh, FF_, D_, D_, 1);

        // W2: split-K partials + fused reduce/residual/LN
        gemm_h<<<gSK, 256, GSMEM>>>(hh, lw2, nullptr, pbuf, D_, FF_, FF_ / KS_, 4);
        ln3_kernel<<<M_/8, 256>>>(x, pbuf, b2 + (size_t)i*D_,
                                  ln2g + (size_t)i*D_, ln2b + (size_t)i*D_, x, xh);
    }

    top_kernel<<<B_, 256>>>(fts, Wtop, btop, out);
}

// round 12
// speedup vs baseline: 1.9471x; 1.0971x over previous
#include <cuda_runtime.h>
#include <cuda_fp16.h>
#include <math.h>
#include <stdint.h>

#define B_ 2
#define S_ 2048
#define D_ 768
#define H_ 12
#define HD_ 64
#define FF_ 3072
#define L_ 12
#define M_ (B_*S_)   // 4096 rows
#define D3_ (3*D_)   // 2304
#define KS_ 3        // split-K factor for N=768 GEMMs

// ---------------- scratch (device globals; no allocation allowed) ----------
__device__ float g_x[M_*D_];
__device__ float g_p[KS_*M_*D_];                 // split-K partials

__device__ __align__(16) __half g_xh[M_*D_];     // fp16 x (GEMM A input)
__device__ __align__(16) __half g_ah[M_*D_];     // fp16 attention out
__device__ __align__(16) __half g_hh[M_*FF_];    // fp16 gelu out
__device__ __align__(16) __half g_qkv[M_*D3_];   // fused q|k|v rows
// transposed fp16 weights, ALL layers
__device__ __align__(16) __half g_wqkv[L_*D3_*D_];  // [L][2304][768]
__device__ __align__(16) __half g_wo[L_*D_*D_];
__device__ __align__(16) __half g_w1[L_*FF_*D_];    // N=3072,K=768
__device__ __align__(16) __half g_w2[L_*D_*FF_];    // N=768,K=3072
__device__ float g_bqkv[L_*D3_];

// ---------------- PTX helpers (base-target safe) ----------------
__device__ __forceinline__ uint32_t smem_u32(const void* p) {
    uint32_t a;
    asm("{ .reg .u64 t; cvta.to.shared.u64 t, %1; cvt.u32.u64 %0, t; }" : "=r"(a) : "l"(p));
    return a;
}
__device__ __forceinline__ void cp16(uint32_t s, const void* g) {
    asm volatile("cp.async.cg.shared.global [%0], [%1], 16;" :: "r"(s), "l"(g));
}
#define CP_COMMIT()  asm volatile("cp.async.commit_group;" ::: "memory")
#define CP_WAIT(n)   asm volatile("cp.async.wait_group %0;" :: "n"(n) : "memory")

__device__ __forceinline__ void ldm4(uint32_t* r, uint32_t addr) {
    asm volatile("ldmatrix.sync.aligned.m8n8.x4.shared.b16 {%0,%1,%2,%3}, [%4];"
        : "=r"(r[0]), "=r"(r[1]), "=r"(r[2]), "=r"(r[3]) : "r"(addr));
}
__device__ __forceinline__ void ldm4t(uint32_t* r, uint32_t addr) {
    asm volatile("ldmatrix.sync.aligned.m8n8.x4.trans.shared.b16 {%0,%1,%2,%3}, [%4];"
        : "=r"(r[0]), "=r"(r[1]), "=r"(r[2]), "=r"(r[3]) : "r"(addr));
}
__device__ __forceinline__ void mma16816(float* c, const uint32_t* a, uint32_t b0, uint32_t b1) {
    asm volatile("mma.sync.aligned.m16n8k16.row.col.f32.f16.f16.f32 "
        "{%0,%1,%2,%3}, {%4,%5,%6,%7}, {%8,%9}, {%0,%1,%2,%3};"
        : "+f"(c[0]), "+f"(c[1]), "+f"(c[2]), "+f"(c[3])
        : "r"(a[0]), "r"(a[1]), "r"(a[2]), "r"(a[3]), "r"(b0), "r"(b1));
}
__device__ __forceinline__ uint32_t packh2(float a, float b) {
    __half2 h = __floats2half2_rn(a, b);
    return *reinterpret_cast<uint32_t*>(&h);
}

// ---------------- batched weight transpose -------------------------------
__global__ void ttrans_all(const float* __restrict__ W, __half* __restrict__ T,
                           int K, int N, size_t lsW, size_t lsT) {
    __shared__ float t[32][33];
    int li = blockIdx.z;
    const float* Wl = W + (size_t)li * lsW;
    __half* Tl = T + (size_t)li * lsT;
    int k0 = blockIdx.y * 32, n0 = blockIdx.x * 32;
    int tx = threadIdx.x & 31, ty = threadIdx.x >> 5;  // 32 x 8
#pragma unroll
    for (int i = 0; i < 4; i++)
        t[ty + i * 8][tx] = Wl[(size_t)(k0 + ty + i * 8) * N + n0 + tx];
    __syncthreads();
#pragma unroll
    for (int i = 0; i < 4; i++)
        Tl[(size_t)(n0 + ty + i * 8) * K + k0 + tx] = __float2half(t[tx][ty + i * 8]);
}

// concat biases: [L][D] x3 -> [L][3D]
__global__ void bcat_kernel(const float* __restrict__ bq, const float* __restrict__ bk,
                            const float* __restrict__ bv) {
    int i = blockIdx.x * blockDim.x + threadIdx.x;
    if (i >= L_ * D3_) return;
    int li = i / D3_, r = i % D3_;
    int sec = r / D_, d = r % D_;
    const float* src = sec == 0 ? bq : (sec == 1 ? bk : bv);
    g_bqkv[i] = src[li * D_ + d];
}

__device__ __forceinline__ float gelu_f(float c) {
    return 0.5f * c * (1.0f + erff(c * 0.70710678118654752f));
}

// ================= GEMM: CTA 256x128, BK=64, 3-stage cp.async =============
// A: [M,Kfull] fp16 K-major. B: [N,Kfull] fp16 K-major.
// Each CTA processes Keff of K starting at blockIdx.z*Keff.
// epi: 1 gelu (fp16 out), 3 bias-only (fp16 out), 4 split-K partial (f32)
#define PITCH   144                // 64 halves (128B) + 16B pad
#define TA      (256*PITCH)        // 36864
#define TB      (128*PITCH)        // 18432
#define STAGE   (TA+TB)            // 55296
#define GSMEM   (3*STAGE)          // 165888

__device__ __forceinline__ void load_chunk(uint32_t sbase,
                                           const __half* pA, const __half* pB,
                                           int K, int tid) {
#pragma unroll
    for (int e = 0; e < 8; e++) {       // A: 256 rows x 8 chunks = 2048
        int idx = tid + e * 256;
        int r = idx >> 3, ch = idx & 7;
        cp16(sbase + r * PITCH + ch * 16, pA + (size_t)r * K + ch * 8);
    }
#pragma unroll
    for (int e = 0; e < 4; e++) {       // B: 128 rows x 8 chunks = 1024
        int idx = tid + e * 256;
        int r = idx >> 3, ch = idx & 7;
        cp16(sbase + TA + r * PITCH + ch * 16, pB + (size_t)r * K + ch * 8);
    }
}

__global__ void __launch_bounds__(256, 1)
gemm_h(const __half* __restrict__ A, const __half* __restrict__ Bt,
       const float* __restrict__ bias,
       void* __restrict__ Cv, int N, int Kfull, int Keff, int epi) {
    extern __shared__ __align__(16) char smem[];
    uint32_t sb = smem_u32(smem);
    int tid = threadIdx.x, wid = tid >> 5, lane = tid & 31;
    int wm = wid >> 1, wn = wid & 1;       // warp tile: 64 x 64
    int m0 = blockIdx.y * 256, n0 = blockIdx.x * 128;
    int z = blockIdx.z;

    const __half* pA = A  + (size_t)m0 * Kfull + (size_t)z * Keff;
    const __half* pB = Bt + (size_t)n0 * Kfull + (size_t)z * Keff;

    float acc[4][8][4] = {};

    const int NC = Keff / 64;
    load_chunk(sb, pA, pB, Kfull, tid);
    CP_COMMIT();
    if (NC > 1) {
        load_chunk(sb + STAGE, pA + 64, pB + 64, Kfull, tid);
        CP_COMMIT();
    }

    int lrow = lane & 15;
    int lch  = (lane >> 4) * 16;

    for (int c = 0; c < NC; c++) {
        if (c + 2 < NC) { CP_WAIT(1); } else { CP_WAIT(0); }
        __syncthreads();
        if (c + 2 < NC) {
            int ns = (c + 2) % 3;
            load_chunk(sb + ns * STAGE, pA + (c+2)*64, pB + (c+2)*64, Kfull, tid);
            CP_COMMIT();
        }
        uint32_t st = sb + (c % 3) * STAGE;

#pragma unroll
        for (int ks = 0; ks < 4; ks++) {
            uint32_t ah[4][4], bh[4][4];
#pragma unroll
            for (int mi = 0; mi < 4; mi++) {
                uint32_t off = (uint32_t)(wm*64 + mi*16 + lrow) * PITCH + ks*32 + lch;
                ldm4(ah[mi], st + off);
            }
#pragma unroll
            for (int np = 0; np < 4; np++) {
                uint32_t off = (uint32_t)(wn*64 + np*16 + lrow) * PITCH + ks*32 + lch;
                ldm4(bh[np], st + TA + off);
            }
#pragma unroll
            for (int mi = 0; mi < 4; mi++)
#pragma unroll
                for (int ni = 0; ni < 8; ni++) {
                    int np = ni >> 1, sel = ni & 1;
                    mma16816(acc[mi][ni], ah[mi], bh[np][sel], bh[np][sel + 2]);
                }
        }
    }

    int qrow = lane >> 2, qcol = (lane & 3) * 2;
#pragma unroll
    for (int mi = 0; mi < 4; mi++) {
#pragma unroll
        for (int ni = 0; ni < 8; ni++) {
            int row = m0 + wm*64 + mi*16 + qrow;
            int col = n0 + wn*64 + ni*8 + qcol;
#pragma unroll
            for (int hh = 0; hh < 2; hh++) {
                int r = row + hh * 8;
                float v0 = acc[mi][ni][hh*2 + 0];
                float v1 = acc[mi][ni][hh*2 + 1];
                if (epi == 4) {
                    *(float2*)((float*)Cv + (size_t)z * M_ * N + (size_t)r * N + col) =
                        make_float2(v0, v1);
                } else {
                    v0 += bias[col]; v1 += bias[col + 1];
                    if (epi == 1) { v0 = gelu_f(v0); v1 = gelu_f(v1); }
                    *(__half2*)((__half*)Cv + (size_t)r * N + col) = __floats2half2_rn(v0, v1);
                }
            }
        }
    }
}

// ---------------- reductions ----------------
__device__ __forceinline__ float warp_sum(float v) {
#pragma unroll
    for (int o = 16; o; o >>= 1) v += __shfl_xor_sync(0xffffffffu, v, o);
    return v;
}

// ---------------- fused split-K reduce + residual + bias + LN -------------
__global__ void __launch_bounds__(256)
ln3_kernel(const float* __restrict__ xres, const float* __restrict__ P,
           const float* __restrict__ bias, const float* __restrict__ g,
           const float* __restrict__ b, float* __restrict__ out,
           __half* __restrict__ outh) {
    int wid = threadIdx.x >> 5, lane = threadIdx.x & 31;
    int row = blockIdx.x * 8 + wid;
    const float* r0 = xres + (size_t)row * D_;
    const float* p0 = P + (size_t)row * D_;
    const float* p1 = P + (size_t)M_ * D_ + (size_t)row * D_;
    const float* p2 = P + 2 * (size_t)M_ * D_ + (size_t)row * D_;
    float vals[24];
    float s = 0.f, sq = 0.f;
#pragma unroll
    for (int i = 0; i < 24; i++) {
        int d = lane + i * 32;
        vals[i] = r0[d] + ((p0[d] + p1[d]) + p2[d]) + bias[d];
        s += vals[i]; sq += vals[i] * vals[i];
    }
    s = warp_sum(s); sq = warp_sum(sq);
    float mean = s * (1.0f / D_);
    float var = sq * (1.0f / D_) - mean * mean;
    float inv = rsqrtf(var + 1e-5f);
#pragma unroll
    for (int i = 0; i < 24; i++) {
        int d = lane + i * 32;
        float rr = (vals[i] - mean) * inv * g[d] + b[d];
        out[(size_t)row * D_ + d] = rr;
        outh[(size_t)row * D_ + d] = __float2half(rr);
    }
}

__global__ void __launch_bounds__(256)
embed_ln_kernel(const int* __restrict__ ids, const float* __restrict__ we,
                const float* __restrict__ pe, const float* __restrict__ te,
                const float* __restrict__ g, const float* __restrict__ b) {
    int wid = threadIdx.x >> 5, lane = threadIdx.x & 31;
    int row = blockIdx.x * 8 + wid;
    int s_ = row % S_;
    int id = ids[row];
    float vals[24];
    float s = 0.f, sq = 0.f;
#pragma unroll
    for (int i = 0; i < 24; i++) {
        int d = lane + i * 32;
        vals[i] = we[(size_t)id * D_ + d] + pe[(size_t)(s_ + 2) * D_ + d] + te[d];
        s += vals[i]; sq += vals[i] * vals[i];
    }
    s = warp_sum(s); sq = warp_sum(sq);
    float mean = s * (1.0f / D_);
    float var = sq * (1.0f / D_) - mean * mean;
    float inv = rsqrtf(var + 1e-5f);
#pragma unroll
    for (int i = 0; i < 24; i++) {
        int d = lane + i * 32;
        float rr = (vals[i] - mean) * inv * g[d] + b[d];
        g_x[(size_t)row * D_ + d] = rr;
        g_xh[(size_t)row * D_ + d] = __float2half(rr);
    }
}

// ---------------- tensor-core banded attention ----------------
__global__ void __launch_bounds__(256)
attn_mma(const __half* __restrict__ qkv, const float* __restrict__ mask,
         __half* __restrict__ outh, int half) {
    __shared__ __align__(16) __half qs[128][72];
    __shared__ __align__(16) __half ks[32][72];
    __shared__ __align__(16) __half vs[32][72];
    __shared__ float kadd[32];
    int tid = threadIdx.x, wid = tid >> 5, lane = tid & 31;
    int qt = blockIdx.x * 128;
    int bh = blockIdx.y;
    int b = bh / H_, h = bh % H_;
    const size_t base = (size_t)b * S_;

#pragma unroll
    for (int i = 0; i < 4; i++) {
        int idx = tid + i * 256;
        int r = idx >> 3, seg = idx & 7;
        *(uint4*)&qs[r][seg * 8] =
            *(const uint4*)(qkv + (base + qt + r) * D3_ + h * HD_ + seg * 8);
    }
    __syncthreads();

    uint32_t qa[4][4];
    {
        int r = wid * 16 + (lane & 15);
        int cc = (lane >> 4) * 8;
#pragma unroll
        for (int k4 = 0; k4 < 4; k4++)
            ldm4(qa[k4], smem_u32(&qs[r][k4 * 16 + cc]));
    }

    float m0 = -1e30f, m1 = -1e30f, l0 = 0.f, l1 = 0.f;
    float oa[8][4];
#pragma unroll
    for (int t = 0; t < 8; t++) { oa[t][0]=0.f; oa[t][1]=0.f; oa[t][2]=0.f; oa[t][3]=0.f; }

    int qg0 = qt + wid * 16 + (lane >> 2);
    int qg1 = qg0 + 8;
    int kcol = (lane & 3) * 2;

    int kt0 = qt - half; if (kt0 < 0) kt0 = 0; kt0 >>= 5;
    int kt1 = qt + 127 + half; if (kt1 > S_ - 1) kt1 = S_ - 1; kt1 >>= 5;

    for (int kt = kt0; kt <= kt1; kt++) {
        int j0 = kt * 32;
        __syncthreads();
        {
            int r = tid >> 3, seg = tid & 7;
            const __half* rp = qkv + (base + j0 + r) * D3_ + h * HD_ + seg * 8;
            *(uint4*)&ks[r][seg * 8] = *(const uint4*)(rp + D_);
            *(uint4*)&vs[r][seg * 8] = *(const uint4*)(rp + 2 * D_);
        }
        if (tid < 32) kadd[tid] = (1.0f - mask[base + j0 + tid]) * -1e9f;
        __syncthreads();

        float sa[4][4] = {};
        {
            int rr = lane & 15, cc = (lane >> 4) * 8;
#pragma unroll
            for (int k4 = 0; k4 < 4; k4++) {
                uint32_t kb0[4], kb1[4];
                ldm4(kb0, smem_u32(&ks[rr][k4 * 16 + cc]));
                ldm4(kb1, smem_u32(&ks[16 + rr][k4 * 16 + cc]));
                mma16816(sa[0], qa[k4], kb0[0], kb0[2]);
                mma16816(sa[1], qa[k4], kb0[1], kb0[3]);
                mma16816(sa[2], qa[k4], kb1[0], kb1[2]);
                mma16816(sa[3], qa[k4], kb1[1], kb1[3]);
            }
        }

        float mt0 = -1e30f, mt1 = -1e30f;
#pragma unroll
        for (int nt = 0; nt < 4; nt++) {
            float2 ka2 = *(float2*)&kadd[nt * 8 + kcol];
#pragma unroll
            for (int e = 0; e < 2; e++) {
                int key = j0 + nt * 8 + kcol + e;
                float ka = e ? ka2.y : ka2.x;
                float s0 = sa[nt][e] * 0.125f + ka;
                float s1 = sa[nt][2 + e] * 0.125f + ka;
                if (key < qg0 - half || key > qg0 + half) s0 = -1e9f;
                if (key < qg1 - half || key > qg1 + half) s1 = -1e9f;
                sa[nt][e] = s0; sa[nt][2 + e] = s1;
                mt0 = fmaxf(mt0, s0); mt1 = fmaxf(mt1, s1);
            }
        }
        mt0 = fmaxf(mt0, __shfl_xor_sync(0xffffffffu, mt0, 1));
        mt0 = fmaxf(mt0, __shfl_xor_sync(0xffffffffu, mt0, 2));
        mt1 = fmaxf(mt1, __shfl_xor_sync(0xffffffffu, mt1, 1));
        mt1 = fmaxf(mt1, __shfl_xor_sync(0xffffffffu, mt1, 2));
        float mn0 = fmaxf(m0, mt0), mn1 = fmaxf(m1, mt1);
        float sc0 = __expf(m0 - mn0), sc1 = __expf(m1 - mn1);
        m0 = mn0; m1 = mn1;

        float ls0 = 0.f, ls1 = 0.f;
        uint32_t pa[2][4];
#pragma unroll
        for (int nt = 0; nt < 4; nt++) {
            float p0 = __expf(sa[nt][0] - mn0);
            float p1 = __expf(sa[nt][1] - mn0);
            float p2 = __expf(sa[nt][2] - mn1);
            float p3 = __expf(sa[nt][3] - mn1);
            ls0 += p0 + p1; ls1 += p2 + p3;
            int kst = nt >> 1, hi = (nt & 1) * 2;
            pa[kst][hi + 0] = packh2(p0, p1);
            pa[kst][hi + 1] = packh2(p2, p3);
        }
        ls0 += __shfl_xor_sync(0xffffffffu, ls0, 1);
        ls0 += __shfl_xor_sync(0xffffffffu, ls0, 2);
        ls1 += __shfl_xor_sync(0xffffffffu, ls1, 1);
        ls1 += __shfl_xor_sync(0xffffffffu, ls1, 2);
        l0 = l0 * sc0 + ls0; l1 = l1 * sc1 + ls1;

#pragma unroll
        for (int t = 0; t < 8; t++) {
            oa[t][0] *= sc0; oa[t][1] *= sc0; oa[t][2] *= sc1; oa[t][3] *= sc1;
        }

        {
            int rr = lane & 15, cc = (lane >> 4) * 8;
#pragma unroll
            for (int kst = 0; kst < 2; kst++) {
#pragma unroll
                for (int dg = 0; dg < 4; dg++) {
                    uint32_t vb[4];
                    ldm4t(vb, smem_u32(&vs[kst * 16 + rr][dg * 16 + cc]));
                    mma16816(oa[dg * 2],     pa[kst], vb[0], vb[1]);
                    mma16816(oa[dg * 2 + 1], pa[kst], vb[2], vb[3]);
                }
            }
        }
    }

    float inv0 = 1.0f / l0, inv1 = 1.0f / l1;
    __half* op0 = outh + (base + qg0) * D_ + h * HD_;
    __half* op1 = outh + (base + qg1) * D_ + h * HD_;
#pragma unroll
    for (int t = 0; t < 8; t++) {
        int dim = t * 8 + kcol;
        *(__half2*)(op0 + dim) = __floats2half2_rn(oa[t][0] * inv0, oa[t][1] * inv0);
        *(__half2*)(op1 + dim) = __floats2half2_rn(oa[t][2] * inv1, oa[t][3] * inv1);
    }
}

// ---------------- top head ----------------
__global__ void top_kernel(const float* __restrict__ fts,
                           const float* __restrict__ Wtop,
                           const float* __restrict__ btop,
                           float* __restrict__ out) {
    int b = blockIdx.x;
    int lane = threadIdx.x & 31, wid = threadIdx.x >> 5;
    __shared__ float sw[8];
    const float* cls = g_x + (size_t)b * S_ * D_;
    float part = 0.f;
    for (int d = threadIdx.x; d < D_; d += 256) part += cls[d] * Wtop[d];
    part = warp_sum(part);
    if (lane == 0) sw[wid] = part;
    __syncthreads();
    if (threadIdx.x == 0) {
        float r = 0.f;
#pragma unroll
        for (int i = 0; i < 8; i++) r += sw[i];
        out[b] = r + fts[b] * Wtop[D_] + btop[0];
    }
}

// ---------------- host driver ----------------
extern "C" void kernel_launch(void* const* d_in, const int* in_sizes, int n_in,
                              void* d_out, int out_size) {
    const int*   ids  = (const int*)  d_in[0];
    const float* mask = (const float*)d_in[1];
    const float* fts  = (const float*)d_in[2];
    const float* we   = (const float*)d_in[3];
    const float* pe   = (const float*)d_in[4];
    const float* te   = (const float*)d_in[5];
    const float* ln_eg= (const float*)d_in[6];
    const float* ln_eb= (const float*)d_in[7];
    const float* Wq   = (const float*)d_in[8];
    const float* bq   = (const float*)d_in[9];
    const float* Wk   = (const float*)d_in[10];
    const float* bk   = (const float*)d_in[11];
    const float* Wv   = (const float*)d_in[12];
    const float* bv   = (const float*)d_in[13];
    const float* Wo   = (const float*)d_in[14];
    const float* bo   = (const float*)d_in[15];
    const float* ln1g = (const float*)d_in[16];
    const float* ln1b = (const float*)d_in[17];
    const float* W1   = (const float*)d_in[18];
    const float* b1   = (const float*)d_in[19];
    const float* W2   = (const float*)d_in[20];
    const float* b2   = (const float*)d_in[21];
    const float* ln2g = (const float*)d_in[22];
    const float* ln2b = (const float*)d_in[23];
    const float* Wtop = (const float*)d_in[24];
    const float* btop = (const float*)d_in[25];
    float* out = (float*)d_out;

    float *x, *pbuf, *bqkv;
    cudaGetSymbolAddress((void**)&x,  g_x);
    cudaGetSymbolAddress((void**)&pbuf, g_p);
    cudaGetSymbolAddress((void**)&bqkv, g_bqkv);

    __half *xh, *ah, *hh, *qkv, *wqkv, *wo, *w1, *w2;
    cudaGetSymbolAddress((void**)&xh, g_xh);
    cudaGetSymbolAddress((void**)&ah, g_ah);
    cudaGetSymbolAddress((void**)&hh, g_hh);
    cudaGetSymbolAddress((void**)&qkv, g_qkv);
    cudaGetSymbolAddress((void**)&wqkv, g_wqkv);
    cudaGetSymbolAddress((void**)&wo, g_wo);
    cudaGetSymbolAddress((void**)&w1, g_w1);
    cudaGetSymbolAddress((void**)&w2, g_w2);

    cudaFuncSetAttribute(gemm_h, cudaFuncAttributeMaxDynamicSharedMemorySize, GSMEM);

    static const int halves[L_] = {16,16,32,32,64,64,128,128,256,256,256,256};

    embed_ln_kernel<<<M_/8, 256>>>(ids, we, pe, te, ln_eg, ln_eb);

    // weight prep (batched over layers)
    dim3 tD(D_ / 32, D_ / 32, L_);
    dim3 t1(FF_ / 32, D_ / 32, L_);
    dim3 t2(D_ / 32, FF_ / 32, L_);
    size_t lsD = (size_t)D_ * D_, lsQKV = (size_t)D3_ * D_;
    ttrans_all<<<tD, 256>>>(Wq, wqkv + 0 * lsD, D_, D_, lsD, lsQKV);
    ttrans_all<<<tD, 256>>>(Wk, wqkv + 1 * lsD, D_, D_, lsD, lsQKV);
    ttrans_all<<<tD, 256>>>(Wv, wqkv + 2 * lsD, D_, D_, lsD, lsQKV);
    ttrans_all<<<tD, 256>>>(Wo, wo, D_, D_, lsD, lsD);
    ttrans_all<<<t1, 256>>>(W1, w1, D_, FF_, (size_t)D_*FF_, (size_t)FF_*D_);
    ttrans_all<<<t2, 256>>>(W2, w2, FF_, D_, (size_t)FF_*D_, (size_t)D_*FF_);
    bcat_kernel<<<(L_*D3_ + 255)/256, 256>>>(bq, bk, bv);

    dim3 gQKV(D3_ / 128, M_ / 256, 1);   // (18, 16) = 288 CTAs
    dim3 gF(FF_ / 128, M_ / 256, 1);     // (24, 16) = 384 CTAs
    dim3 gSK(D_ / 128, M_ / 256, KS_);   // (6, 16, 3) = 288 CTAs split-K
    dim3 ga(S_ / 128, B_ * H_);          // (16, 24) = 384 blocks

    for (int i = 0; i < L_; i++) {
        __half* lwqkv = wqkv + (size_t)i * lsQKV;
        __half* lwo = wo + (size_t)i * lsD;
        __half* lw1 = w1 + (size_t)i * FF_ * D_;
        __half* lw2 = w2 + (size_t)i * D_ * FF_;

        gemm_h<<<gQKV, 256, GSMEM>>>(xh, lwqkv, bqkv + (size_t)i*D3_, qkv, D3_, D_, D_, 3);

        attn_mma<<<ga, 256>>>(qkv, mask, ah, halves[i]);

        // Wo: split-K partials + fused reduce/residual/LN
        gemm_h<<<gSK, 256, GSMEM>>>(ah, lwo, nullptr, pbuf, D_, D_, D_ / KS_, 4);
        ln3_kernel<<<M_/8, 256>>>(x, pbuf, bo + (size_t)i*D_,
                                  ln1g + (size_t)i*D_, ln1b + (size_t)i*D_, x, xh);

        gemm_h<<<gF, 256, GSMEM>>>(xh, lw1, b1 + (size_t)i*FF_, hh, FF_, D_, D_, 1);

        // W2: split-K partials + fused reduce/residual/LN
        gemm_h<<<gSK, 256, GSMEM>>>(hh, lw2, nullptr, pbuf, D_, FF_, FF_ / KS_, 4);
        ln3_kernel<<<M_/8, 256>>>(x, pbuf, b2 + (size_t)i*D_,
                                  ln2g + (size_t)i*D_, ln2b + (size_t)i*D_, x, xh);
    }

    top_kernel<<<B_, 256>>>(fts, Wtop, btop, out);
}

// round 13
// speedup vs baseline: 1.9702x; 1.0118x over previous
#include <cuda_runtime.h>
#include <cuda_fp16.h>
#include <math.h>
#include <stdint.h>

#define B_ 2
#define S_ 2048
#define D_ 768
#define H_ 12
#define HD_ 64
#define FF_ 3072
#define L_ 12
#define M_ (B_*S_)   // 4096 rows
#define D3_ (3*D_)   // 2304
#define KS_ 3        // split-K factor for N=768 GEMMs

// ---------------- scratch (device globals; no allocation allowed) ----------
__device__ float g_x[M_*D_];
__device__ float g_p[KS_*M_*D_];                 // split-K partials

__device__ __align__(16) __half g_xh[M_*D_];     // fp16 x (GEMM A input)
__device__ __align__(16) __half g_ah[M_*D_];     // fp16 attention out
__device__ __align__(16) __half g_hh[M_*FF_];    // fp16 gelu out
__device__ __align__(16) __half g_qkv[M_*D3_];   // fused q|k|v rows
// transposed fp16 weights, ALL layers
__device__ __align__(16) __half g_wqkv[L_*D3_*D_];  // [L][2304][768]
__device__ __align__(16) __half g_wo[L_*D_*D_];
__device__ __align__(16) __half g_w1[L_*FF_*D_];    // N=3072,K=768
__device__ __align__(16) __half g_w2[L_*D_*FF_];    // N=768,K=3072
__device__ float g_bqkv[L_*D3_];

// ---------------- PTX helpers (base-target safe) ----------------
__device__ __forceinline__ uint32_t smem_u32(const void* p) {
    uint32_t a;
    asm("{ .reg .u64 t; cvta.to.shared.u64 t, %1; cvt.u32.u64 %0, t; }" : "=r"(a) : "l"(p));
    return a;
}
__device__ __forceinline__ void cp16(uint32_t s, const void* g) {
    asm volatile("cp.async.cg.shared.global [%0], [%1], 16;" :: "r"(s), "l"(g));
}
#define CP_COMMIT()  asm volatile("cp.async.commit_group;" ::: "memory")
#define CP_WAIT(n)   asm volatile("cp.async.wait_group %0;" :: "n"(n) : "memory")

__device__ __forceinline__ void ldm4(uint32_t* r, uint32_t addr) {
    asm volatile("ldmatrix.sync.aligned.m8n8.x4.shared.b16 {%0,%1,%2,%3}, [%4];"
        : "=r"(r[0]), "=r"(r[1]), "=r"(r[2]), "=r"(r[3]) : "r"(addr));
}
__device__ __forceinline__ void ldm4t(uint32_t* r, uint32_t addr) {
    asm volatile("ldmatrix.sync.aligned.m8n8.x4.trans.shared.b16 {%0,%1,%2,%3}, [%4];"
        : "=r"(r[0]), "=r"(r[1]), "=r"(r[2]), "=r"(r[3]) : "r"(addr));
}
__device__ __forceinline__ void mma16816(float* c, const uint32_t* a, uint32_t b0, uint32_t b1) {
    asm volatile("mma.sync.aligned.m16n8k16.row.col.f32.f16.f16.f32 "
        "{%0,%1,%2,%3}, {%4,%5,%6,%7}, {%8,%9}, {%0,%1,%2,%3};"
        : "+f"(c[0]), "+f"(c[1]), "+f"(c[2]), "+f"(c[3])
        : "r"(a[0]), "r"(a[1]), "r"(a[2]), "r"(a[3]), "r"(b0), "r"(b1));
}
__device__ __forceinline__ uint32_t packh2(float a, float b) {
    __half2 h = __floats2half2_rn(a, b);
    return *reinterpret_cast<uint32_t*>(&h);
}

// ---------------- batched weight transpose -------------------------------
__global__ void ttrans_all(const float* __restrict__ W, __half* __restrict__ T,
                           int K, int N, size_t lsW, size_t lsT) {
    __shared__ float t[32][33];
    int li = blockIdx.z;
    const float* Wl = W + (size_t)li * lsW;
    __half* Tl = T + (size_t)li * lsT;
    int k0 = blockIdx.y * 32, n0 = blockIdx.x * 32;
    int tx = threadIdx.x & 31, ty = threadIdx.x >> 5;  // 32 x 8
#pragma unroll
    for (int i = 0; i < 4; i++)
        t[ty + i * 8][tx] = Wl[(size_t)(k0 + ty + i * 8) * N + n0 + tx];
    __syncthreads();
#pragma unroll
    for (int i = 0; i < 4; i++)
        Tl[(size_t)(n0 + ty + i * 8) * K + k0 + tx] = __float2half(t[tx][ty + i * 8]);
}

// concat biases: [L][D] x3 -> [L][3D]
__global__ void bcat_kernel(const float* __restrict__ bq, const float* __restrict__ bk,
                            const float* __restrict__ bv) {
    int i = blockIdx.x * blockDim.x + threadIdx.x;
    if (i >= L_ * D3_) return;
    int li = i / D3_, r = i % D3_;
    int sec = r / D_, d = r % D_;
    const float* src = sec == 0 ? bq : (sec == 1 ? bk : bv);
    g_bqkv[i] = src[li * D_ + d];
}

__device__ __forceinline__ float gelu_f(float c) {
    return 0.5f * c * (1.0f + erff(c * 0.70710678118654752f));
}

// ================= GEMM: CTA 256x128, BK=64, 3-stage cp.async =============
#define PITCH   144                // 64 halves (128B) + 16B pad
#define TA      (256*PITCH)        // 36864
#define TB      (128*PITCH)        // 18432
#define STAGE   (TA+TB)            // 55296
#define GSMEM   (3*STAGE)          // 165888

__device__ __forceinline__ void load_chunk(uint32_t sbase,
                                           const __half* pA, const __half* pB,
                                           int K, int tid) {
#pragma unroll
    for (int e = 0; e < 8; e++) {       // A: 256 rows x 8 chunks = 2048
        int idx = tid + e * 256;
        int r = idx >> 3, ch = idx & 7;
        cp16(sbase + r * PITCH + ch * 16, pA + (size_t)r * K + ch * 8);
    }
#pragma unroll
    for (int e = 0; e < 4; e++) {       // B: 128 rows x 8 chunks = 1024
        int idx = tid + e * 256;
        int r = idx >> 3, ch = idx & 7;
        cp16(sbase + TA + r * PITCH + ch * 16, pB + (size_t)r * K + ch * 8);
    }
}

__global__ void __launch_bounds__(256, 1)
gemm_h(const __half* __restrict__ A, const __half* __restrict__ Bt,
       const float* __restrict__ bias,
       void* __restrict__ Cv, int N, int Kfull, int Keff, int epi) {
    extern __shared__ __align__(16) char smem[];
    uint32_t sb = smem_u32(smem);
    int tid = threadIdx.x, wid = tid >> 5, lane = tid & 31;
    int wm = wid >> 1, wn = wid & 1;       // warp tile: 64 x 64
    int m0 = blockIdx.y * 256, n0 = blockIdx.x * 128;
    int z = blockIdx.z;

    const __half* pA = A  + (size_t)m0 * Kfull + (size_t)z * Keff;
    const __half* pB = Bt + (size_t)n0 * Kfull + (size_t)z * Keff;

    float acc[4][8][4] = {};

    const int NC = Keff / 64;
    load_chunk(sb, pA, pB, Kfull, tid);
    CP_COMMIT();
    if (NC > 1) {
        load_chunk(sb + STAGE, pA + 64, pB + 64, Kfull, tid);
        CP_COMMIT();
    }

    int lrow = lane & 15;
    int lch  = (lane >> 4) * 16;

    for (int c = 0; c < NC; c++) {
        if (c + 2 < NC) { CP_WAIT(1); } else { CP_WAIT(0); }
        __syncthreads();
        if (c + 2 < NC) {
            int ns = (c + 2) % 3;
            load_chunk(sb + ns * STAGE, pA + (c+2)*64, pB + (c+2)*64, Kfull, tid);
            CP_COMMIT();
        }
        uint32_t st = sb + (c % 3) * STAGE;

#pragma unroll
        for (int ks = 0; ks < 4; ks++) {
            uint32_t ah[4][4], bh[4][4];
#pragma unroll
            for (int mi = 0; mi < 4; mi++) {
                uint32_t off = (uint32_t)(wm*64 + mi*16 + lrow) * PITCH + ks*32 + lch;
                ldm4(ah[mi], st + off);
            }
#pragma unroll
            for (int np = 0; np < 4; np++) {
                uint32_t off = (uint32_t)(wn*64 + np*16 + lrow) * PITCH + ks*32 + lch;
                ldm4(bh[np], st + TA + off);
            }
#pragma unroll
            for (int mi = 0; mi < 4; mi++)
#pragma unroll
                for (int ni = 0; ni < 8; ni++) {
                    int np = ni >> 1, sel = ni & 1;
                    mma16816(acc[mi][ni], ah[mi], bh[np][sel], bh[np][sel + 2]);
                }
        }
    }

    int qrow = lane >> 2, qcol = (lane & 3) * 2;
#pragma unroll
    for (int mi = 0; mi < 4; mi++) {
#pragma unroll
        for (int ni = 0; ni < 8; ni++) {
            int row = m0 + wm*64 + mi*16 + qrow;
            int col = n0 + wn*64 + ni*8 + qcol;
#pragma unroll
            for (int hh = 0; hh < 2; hh++) {
                int r = row + hh * 8;
                float v0 = acc[mi][ni][hh*2 + 0];
                float v1 = acc[mi][ni][hh*2 + 1];
                if (epi == 4) {
                    *(float2*)((float*)Cv + (size_t)z * M_ * N + (size_t)r * N + col) =
                        make_float2(v0, v1);
                } else {
                    v0 += bias[col]; v1 += bias[col + 1];
                    if (epi == 1) { v0 = gelu_f(v0); v1 = gelu_f(v1); }
                    *(__half2*)((__half*)Cv + (size_t)r * N + col) = __floats2half2_rn(v0, v1);
                }
            }
        }
    }
}

// ---------------- reductions ----------------
__device__ __forceinline__ float warp_sum(float v) {
#pragma unroll
    for (int o = 16; o; o >>= 1) v += __shfl_xor_sync(0xffffffffu, v, o);
    return v;
}

// ---------------- fused split-K reduce + residual + bias + LN -------------
__global__ void __launch_bounds__(256)
ln3_kernel(const float* __restrict__ xres, const float* __restrict__ P,
           const float* __restrict__ bias, const float* __restrict__ g,
           const float* __restrict__ b, float* __restrict__ out,
           __half* __restrict__ outh) {
    int wid = threadIdx.x >> 5, lane = threadIdx.x & 31;
    int row = blockIdx.x * 8 + wid;
    const float* r0 = xres + (size_t)row * D_;
    const float* p0 = P + (size_t)row * D_;
    const float* p1 = P + (size_t)M_ * D_ + (size_t)row * D_;
    const float* p2 = P + 2 * (size_t)M_ * D_ + (size_t)row * D_;
    float vals[24];
    float s = 0.f, sq = 0.f;
#pragma unroll
    for (int i = 0; i < 24; i++) {
        int d = lane + i * 32;
        vals[i] = r0[d] + ((p0[d] + p1[d]) + p2[d]) + bias[d];
        s += vals[i]; sq += vals[i] * vals[i];
    }
    s = warp_sum(s); sq = warp_sum(sq);
    float mean = s * (1.0f / D_);
    float var = sq * (1.0f / D_) - mean * mean;
    float inv = rsqrtf(var + 1e-5f);
#pragma unroll
    for (int i = 0; i < 24; i++) {
        int d = lane + i * 32;
        float rr = (vals[i] - mean) * inv * g[d] + b[d];
        out[(size_t)row * D_ + d] = rr;
        outh[(size_t)row * D_ + d] = __float2half(rr);
    }
}

__global__ void __launch_bounds__(256)
embed_ln_kernel(const int* __restrict__ ids, const float* __restrict__ we,
                const float* __restrict__ pe, const float* __restrict__ te,
                const float* __restrict__ g, const float* __restrict__ b) {
    int wid = threadIdx.x >> 5, lane = threadIdx.x & 31;
    int row = blockIdx.x * 8 + wid;
    int s_ = row % S_;
    int id = ids[row];
    float vals[24];
    float s = 0.f, sq = 0.f;
#pragma unroll
    for (int i = 0; i < 24; i++) {
        int d = lane + i * 32;
        vals[i] = we[(size_t)id * D_ + d] + pe[(size_t)(s_ + 2) * D_ + d] + te[d];
        s += vals[i]; sq += vals[i] * vals[i];
    }
    s = warp_sum(s); sq = warp_sum(sq);
    float mean = s * (1.0f / D_);
    float var = sq * (1.0f / D_) - mean * mean;
    float inv = rsqrtf(var + 1e-5f);
#pragma unroll
    for (int i = 0; i < 24; i++) {
        int d = lane + i * 32;
        float rr = (vals[i] - mean) * inv * g[d] + b[d];
        g_x[(size_t)row * D_ + d] = rr;
        g_xh[(size_t)row * D_ + d] = __float2half(rr);
    }
}

// ---------------- tensor-core banded attention ----------------
// 128 queries x (b,h); 8 warps x 16 query rows. Double-buffered K/V tiles
// (one __syncthreads per tile) + per-warp band tile skipping.
__global__ void __launch_bounds__(256)
attn_mma(const __half* __restrict__ qkv, const float* __restrict__ mask,
         __half* __restrict__ outh, int half) {
    __shared__ __align__(16) __half qs[128][72];
    __shared__ __align__(16) __half ks[2][32][72];
    __shared__ __align__(16) __half vs[2][32][72];
    __shared__ float kadd[2][32];
    int tid = threadIdx.x, wid = tid >> 5, lane = tid & 31;
    int qt = blockIdx.x * 128;
    int bh = blockIdx.y;
    int b = bh / H_, h = bh % H_;
    const size_t base = (size_t)b * S_;

#pragma unroll
    for (int i = 0; i < 4; i++) {
        int idx = tid + i * 256;
        int r = idx >> 3, seg = idx & 7;
        *(uint4*)&qs[r][seg * 8] =
            *(const uint4*)(qkv + (base + qt + r) * D3_ + h * HD_ + seg * 8);
    }

    int kt0 = qt - half; if (kt0 < 0) kt0 = 0; kt0 >>= 5;
    int kt1 = qt + 127 + half; if (kt1 > S_ - 1) kt1 = S_ - 1; kt1 >>= 5;

    // preload tile kt0 into buffer 0
    int lr = tid >> 3, lseg = tid & 7;
    {
        const __half* rp = qkv + (base + kt0 * 32 + lr) * D3_ + h * HD_ + lseg * 8;
        *(uint4*)&ks[0][lr][lseg * 8] = *(const uint4*)(rp + D_);
        *(uint4*)&vs[0][lr][lseg * 8] = *(const uint4*)(rp + 2 * D_);
        if (tid < 32) kadd[0][tid] = (1.0f - mask[base + kt0 * 32 + tid]) * -1e9f;
    }
    __syncthreads();

    uint32_t qa[4][4];
    {
        int r = wid * 16 + (lane & 15);
        int cc = (lane >> 4) * 8;
#pragma unroll
        for (int k4 = 0; k4 < 4; k4++)
            ldm4(qa[k4], smem_u32(&qs[r][k4 * 16 + cc]));
    }

    float m0 = -1e30f, m1 = -1e30f, l0 = 0.f, l1 = 0.f;
    float oa[8][4];
#pragma unroll
    for (int t = 0; t < 8; t++) { oa[t][0]=0.f; oa[t][1]=0.f; oa[t][2]=0.f; oa[t][3]=0.f; }

    int qg0 = qt + wid * 16 + (lane >> 2);
    int qg1 = qg0 + 8;
    int kcol = (lane & 3) * 2;
    // warp band: queries [qw0, qw0+15]
    int qw0 = qt + wid * 16;
    int wlo = qw0 - half, whi = qw0 + 15 + half;

    for (int kt = kt0; kt <= kt1; kt++) {
        int buf = (kt - kt0) & 1;
        int j0 = kt * 32;

        // issue next tile's global loads into registers
        uint4 nk, nv; float nka = 0.f;
        bool more = (kt < kt1);
        if (more) {
            const __half* rp = qkv + (base + (kt+1) * 32 + lr) * D3_ + h * HD_ + lseg * 8;
            nk = *(const uint4*)(rp + D_);
            nv = *(const uint4*)(rp + 2 * D_);
            if (tid < 32) nka = (1.0f - mask[base + (kt+1) * 32 + tid]) * -1e9f;
        }

        // per-warp band skip
        if (j0 + 31 >= wlo && j0 <= whi) {
            float sa[4][4] = {};
            {
                int rr = lane & 15, cc = (lane >> 4) * 8;
#pragma unroll
                for (int k4 = 0; k4 < 4; k4++) {
                    uint32_t kb0[4], kb1[4];
                    ldm4(kb0, smem_u32(&ks[buf][rr][k4 * 16 + cc]));
                    ldm4(kb1, smem_u32(&ks[buf][16 + rr][k4 * 16 + cc]));
                    mma16816(sa[0], qa[k4], kb0[0], kb0[2]);
                    mma16816(sa[1], qa[k4], kb0[1], kb0[3]);
                    mma16816(sa[2], qa[k4], kb1[0], kb1[2]);
                    mma16816(sa[3], qa[k4], kb1[1], kb1[3]);
                }
            }

            float mt0 = -1e30f, mt1 = -1e30f;
#pragma unroll
            for (int nt = 0; nt < 4; nt++) {
                float2 ka2 = *(float2*)&kadd[buf][nt * 8 + kcol];
#pragma unroll
                for (int e = 0; e < 2; e++) {
                    int key = j0 + nt * 8 + kcol + e;
                    float ka = e ? ka2.y : ka2.x;
                    float s0 = sa[nt][e] * 0.125f + ka;
                    float s1 = sa[nt][2 + e] * 0.125f + ka;
                    if (key < qg0 - half || key > qg0 + half) s0 = -1e9f;
                    if (key < qg1 - half || key > qg1 + half) s1 = -1e9f;
                    sa[nt][e] = s0; sa[nt][2 + e] = s1;
                    mt0 = fmaxf(mt0, s0); mt1 = fmaxf(mt1, s1);
                }
            }
            mt0 = fmaxf(mt0, __shfl_xor_sync(0xffffffffu, mt0, 1));
            mt0 = fmaxf(mt0, __shfl_xor_sync(0xffffffffu, mt0, 2));
            mt1 = fmaxf(mt1, __shfl_xor_sync(0xffffffffu, mt1, 1));
            mt1 = fmaxf(mt1, __shfl_xor_sync(0xffffffffu, mt1, 2));
            float mn0 = fmaxf(m0, mt0), mn1 = fmaxf(m1, mt1);
            float sc0 = __expf(m0 - mn0), sc1 = __expf(m1 - mn1);
            m0 = mn0; m1 = mn1;

            float ls0 = 0.f, ls1 = 0.f;
            uint32_t pa[2][4];
#pragma unroll
            for (int nt = 0; nt < 4; nt++) {
                float p0 = __expf(sa[nt][0] - mn0);
                float p1 = __expf(sa[nt][1] - mn0);
                float p2 = __expf(sa[nt][2] - mn1);
                float p3 = __expf(sa[nt][3] - mn1);
                ls0 += p0 + p1; ls1 += p2 + p3;
                int kst = nt >> 1, hi = (nt & 1) * 2;
                pa[kst][hi + 0] = packh2(p0, p1);
                pa[kst][hi + 1] = packh2(p2, p3);
            }
            ls0 += __shfl_xor_sync(0xffffffffu, ls0, 1);
            ls0 += __shfl_xor_sync(0xffffffffu, ls0, 2);
            ls1 += __shfl_xor_sync(0xffffffffu, ls1, 1);
            ls1 += __shfl_xor_sync(0xffffffffu, ls1, 2);
            l0 = l0 * sc0 + ls0; l1 = l1 * sc1 + ls1;

#pragma unroll
            for (int t = 0; t < 8; t++) {
                oa[t][0] *= sc0; oa[t][1] *= sc0; oa[t][2] *= sc1; oa[t][3] *= sc1;
            }

            {
                int rr = lane & 15, cc = (lane >> 4) * 8;
#pragma unroll
                for (int kst = 0; kst < 2; kst++) {
#pragma unroll
                    for (int dg = 0; dg < 4; dg++) {
                        uint32_t vb[4];
                        ldm4t(vb, smem_u32(&vs[buf][kst * 16 + rr][dg * 16 + cc]));
                        mma16816(oa[dg * 2],     pa[kst], vb[0], vb[1]);
                        mma16816(oa[dg * 2 + 1], pa[kst], vb[2], vb[3]);
                    }
                }
            }
        }

        // store next tile into the other buffer, then sync
        if (more) {
            *(uint4*)&ks[buf ^ 1][lr][lseg * 8] = nk;
            *(uint4*)&vs[buf ^ 1][lr][lseg * 8] = nv;
            if (tid < 32) kadd[buf ^ 1][tid] = nka;
        }
        __syncthreads();
    }

    float inv0 = 1.0f / l0, inv1 = 1.0f / l1;
    __half* op0 = outh + (base + qg0) * D_ + h * HD_;
    __half* op1 = outh + (base + qg1) * D_ + h * HD_;
#pragma unroll
    for (int t = 0; t < 8; t++) {
        int dim = t * 8 + kcol;
        *(__half2*)(op0 + dim) = __floats2half2_rn(oa[t][0] * inv0, oa[t][1] * inv0);
        *(__half2*)(op1 + dim) = __floats2half2_rn(oa[t][2] * inv1, oa[t][3] * inv1);
    }
}

// ---------------- top head ----------------
__global__ void top_kernel(const float* __restrict__ fts,
                           const float* __restrict__ Wtop,
                           const float* __restrict__ btop,
                           float* __restrict__ out) {
    int b = blockIdx.x;
    int lane = threadIdx.x & 31, wid = threadIdx.x >> 5;
    __shared__ float sw[8];
    const float* cls = g_x + (size_t)b * S_ * D_;
    float part = 0.f;
    for (int d = threadIdx.x; d < D_; d += 256) part += cls[d] * Wtop[d];
    part = warp_sum(part);
    if (lane == 0) sw[wid] = part;
    __syncthreads();
    if (threadIdx.x == 0) {
        float r = 0.f;
#pragma unroll
        for (int i = 0; i < 8; i++) r += sw[i];
        out[b] = r + fts[b] * Wtop[D_] + btop[0];
    }
}

// ---------------- host driver ----------------
extern "C" void kernel_launch(void* const* d_in, const int* in_sizes, int n_in,
                              void* d_out, int out_size) {
    const int*   ids  = (const int*)  d_in[0];
    const float* mask = (const float*)d_in[1];
    const float* fts  = (const float*)d_in[2];
    const float* we   = (const float*)d_in[3];
    const float* pe   = (const float*)d_in[4];
    const float* te   = (const float*)d_in[5];
    const float* ln_eg= (const float*)d_in[6];
    const float* ln_eb= (const float*)d_in[7];
    const float* Wq   = (const float*)d_in[8];
    const float* bq   = (const float*)d_in[9];
    const float* Wk   = (const float*)d_in[10];
    const float* bk   = (const float*)d_in[11];
    const float* Wv   = (const float*)d_in[12];
    const float* bv   = (const float*)d_in[13];
    const float* Wo   = (const float*)d_in[14];
    const float* bo   = (const float*)d_in[15];
    const float* ln1g = (const float*)d_in[16];
    const float* ln1b = (const float*)d_in[17];
    const float* W1   = (const float*)d_in[18];
    const float* b1   = (const float*)d_in[19];
    const float* W2   = (const float*)d_in[20];
    const float* b2   = (const float*)d_in[21];
    const float* ln2g = (const float*)d_in[22];
    const float* ln2b = (const float*)d_in[23];
    const float* Wtop = (const float*)d_in[24];
    const float* btop = (const float*)d_in[25];
    float* out = (float*)d_out;

    float *x, *pbuf, *bqkv;
    cudaGetSymbolAddress((void**)&x,  g_x);
    cudaGetSymbolAddress((void**)&pbuf, g_p);
    cudaGetSymbolAddress((void**)&bqkv, g_bqkv);

    __half *xh, *ah, *hh, *qkv, *wqkv, *wo, *w1, *w2;
    cudaGetSymbolAddress((void**)&xh, g_xh);
    cudaGetSymbolAddress((void**)&ah, g_ah);
    cudaGetSymbolAddress((void**)&hh, g_hh);
    cudaGetSymbolAddress((void**)&qkv, g_qkv);
    cudaGetSymbolAddress((void**)&wqkv, g_wqkv);
    cudaGetSymbolAddress((void**)&wo, g_wo);
    cudaGetSymbolAddress((void**)&w1, g_w1);
    cudaGetSymbolAddress((void**)&w2, g_w2);

    cudaFuncSetAttribute(gemm_h, cudaFuncAttributeMaxDynamicSharedMemorySize, GSMEM);

    static const int halves[L_] = {16,16,32,32,64,64,128,128,256,256,256,256};

    embed_ln_kernel<<<M_/8, 256>>>(ids, we, pe, te, ln_eg, ln_eb);

    // weight prep (batched over layers)
    dim3 tD(D_ / 32, D_ / 32, L_);
    dim3 t1(FF_ / 32, D_ / 32, L_);
    dim3 t2(D_ / 32, FF_ / 32, L_);
    size_t lsD = (size_t)D_ * D_, lsQKV = (size_t)D3_ * D_;
    ttrans_all<<<tD, 256>>>(Wq, wqkv + 0 * lsD, D_, D_, lsD, lsQKV);
    ttrans_all<<<tD, 256>>>(Wk, wqkv + 1 * lsD, D_, D_, lsD, lsQKV);
    ttrans_all<<<tD, 256>>>(Wv, wqkv + 2 * lsD, D_, D_, lsD, lsQKV);
    ttrans_all<<<tD, 256>>>(Wo, wo, D_, D_, lsD, lsD);
    ttrans_all<<<t1, 256>>>(W1, w1, D_, FF_, (size_t)D_*FF_, (size_t)FF_*D_);
    ttrans_all<<<t2, 256>>>(W2, w2, FF_, D_, (size_t)FF_*D_, (size_t)D_*FF_);
    bcat_kernel<<<(L_*D3_ + 255)/256, 256>>>(bq, bk, bv);

    dim3 gQKV(D3_ / 128, M_ / 256, 1);   // (18, 16) = 288 CTAs
    dim3 gF(FF_ / 128, M_ / 256, 1);     // (24, 16) = 384 CTAs
    dim3 gSK(D_ / 128, M_ / 256, KS_);   // (6, 16, 3) = 288 CTAs split-K
    dim3 ga(S_ / 128, B_ * H_);          // (16, 24) = 384 blocks

    for (int i = 0; i < L_; i++) {
        __half* lwqkv = wqkv + (size_t)i * lsQKV;
        __half* lwo = wo + (size_t)i * lsD;
        __half* lw1 = w1 + (size_t)i * FF_ * D_;
        __half* lw2 = w2 + (size_t)i * D_ * FF_;

        gemm_h<<<gQKV, 256, GSMEM>>>(xh, lwqkv, bqkv + (size_t)i*D3_, qkv, D3_, D_, D_, 3);

        attn_mma<<<ga, 256>>>(qkv, mask, ah, halves[i]);

        // Wo: split-K partials + fused reduce/residual/LN
        gemm_h<<<gSK, 256, GSMEM>>>(ah, lwo, nullptr, pbuf, D_, D_, D_ / KS_, 4);
        ln3_kernel<<<M_/8, 256>>>(x, pbuf, bo + (size_t)i*D_,
                                  ln1g + (size_t)i*D_, ln1b + (size_t)i*D_, x, xh);

        gemm_h<<<gF, 256, GSMEM>>>(xh, lw1, b1 + (size_t)i*FF_, hh, FF_, D_, D_, 1);

        // W2: split-K partials + fused reduce/residual/LN
        gemm_h<<<gSK, 256, GSMEM>>>(hh, lw2, nullptr, pbuf, D_, FF_, FF_ / KS_, 4);
        ln3_kernel<<<M_/8, 256>>>(x, pbuf, b2 + (size_t)i*D_,
                                  ln2g + (size_t)i*D_, ln2b + (size_t)i*D_, x, xh);
    }

    top_kernel<<<B_, 256>>>(fts, Wtop, btop, out);
}